// round 1
// baseline (speedup 1.0000x reference)
#include <cuda_runtime.h>
#include <math.h>

// Problem constants
#define Bn   4
#define Sn   2048
#define Dn   1024
#define Hn   16
#define DHn  64
#define BHn  (Bn * Hn)          // 64
#define Mn   (Bn * Sn)          // 8192
#define SCALE_F 0.125f          // 1/sqrt(64)

#define OUT_ELEMS  ((size_t)Mn * Dn)            // 8,388,608
#define ATTN_ELEMS ((size_t)BHn * Sn * Sn)      // 268,435,456

// Scratch (device globals — allowed; no runtime allocation)
__device__ float g_q[Mn * Dn];            // [B,H,S,DH]
__device__ float g_k[Mn * Dn];
__device__ float g_v[Mn * Dn];
__device__ float g_ctx[Mn * Dn];          // [B,S,H*DH]
__device__ float g_attn_scratch[ATTN_ELEMS];  // fallback if d_out doesn't hold attn

// ---------------------------------------------------------------------------
// SGEMM with bias: out = X[M,1024] @ W[1024,1024] + bias
// mode 0: out row-major [M,N]
// mode 1: out in head layout [B,H,S,DH]  (m -> (b,s), n -> (h,d))
// blocktile 128x128, BK=8, 256 threads, 8x8 per thread
// ---------------------------------------------------------------------------
__global__ __launch_bounds__(256) void sgemm_bias_kernel(
    const float* __restrict__ X, const float* __restrict__ W,
    const float* __restrict__ bias, float* __restrict__ out, int mode)
{
    const int K = Dn, N = Dn;
    __shared__ float As[8][128];   // transposed: As[k][m]
    __shared__ float Bs[8][128];   // Bs[k][n]

    int tid = threadIdx.x;
    int bm = blockIdx.y * 128;
    int bn = blockIdx.x * 128;
    int tx = tid & 15, ty = tid >> 4;

    float acc[8][8];
#pragma unroll
    for (int i = 0; i < 8; i++)
#pragma unroll
        for (int j = 0; j < 8; j++) acc[i][j] = 0.0f;

    int arow = tid >> 1;            // 0..127
    int acol = (tid & 1) * 4;       // 0 or 4
    int brow = tid >> 5;            // 0..7
    int bcol = (tid & 31) * 4;      // 0..124

    for (int kk = 0; kk < K; kk += 8) {
        float4 a4 = *(const float4*)(X + (size_t)(bm + arow) * K + kk + acol);
        As[acol + 0][arow] = a4.x;
        As[acol + 1][arow] = a4.y;
        As[acol + 2][arow] = a4.z;
        As[acol + 3][arow] = a4.w;
        float4 b4 = *(const float4*)(W + (size_t)(kk + brow) * N + bn + bcol);
        *(float4*)&Bs[brow][bcol] = b4;
        __syncthreads();

#pragma unroll
        for (int k = 0; k < 8; k++) {
            float a[8], b[8];
            *(float4*)&a[0] = *(const float4*)&As[k][ty * 8];
            *(float4*)&a[4] = *(const float4*)&As[k][ty * 8 + 4];
            *(float4*)&b[0] = *(const float4*)&Bs[k][tx * 8];
            *(float4*)&b[4] = *(const float4*)&Bs[k][tx * 8 + 4];
#pragma unroll
            for (int i = 0; i < 8; i++)
#pragma unroll
                for (int j = 0; j < 8; j++) acc[i][j] += a[i] * b[j];
        }
        __syncthreads();
    }

#pragma unroll
    for (int i = 0; i < 8; i++) {
        int m = bm + ty * 8 + i;
#pragma unroll
        for (int j = 0; j < 8; j++) {
            int n = bn + tx * 8 + j;
            float v = acc[i][j] + bias[n];
            if (mode == 0) {
                out[(size_t)m * N + n] = v;
            } else {
                int b = m >> 11, s = m & (Sn - 1);
                int h = n >> 6,  d = n & 63;
                out[(((size_t)b * Hn + h) * Sn + s) * DHn + d] = v;
            }
        }
    }
}

// ---------------------------------------------------------------------------
// Scores: for lower-triangular 64x64 tiles, S_tile = q @ k^T * SCALE
// grid.x = 528 (tri tile id), grid.y = b*H+h
// ---------------------------------------------------------------------------
__global__ __launch_bounds__(256) void scores_kernel(
    const float* __restrict__ q, const float* __restrict__ k,
    float* __restrict__ attn)
{
    int bh = blockIdx.y;
    int t = blockIdx.x;
    int qt = (int)floorf((sqrtf(8.0f * (float)t + 1.0f) - 1.0f) * 0.5f);
    while ((qt + 1) * (qt + 2) / 2 <= t) ++qt;
    while (qt * (qt + 1) / 2 > t) --qt;
    int kt = t - qt * (qt + 1) / 2;

    const float* qb = q + ((size_t)bh * Sn + qt * 64) * DHn;
    const float* kb = k + ((size_t)bh * Sn + kt * 64) * DHn;

    __shared__ float qs[64][65];
    __shared__ float ks[64][65];

    int tid = threadIdx.x;
    for (int i = tid; i < 64 * 16; i += 256) {
        int r = i >> 4, c4 = (i & 15) * 4;
        float4 a = *(const float4*)(qb + (size_t)r * 64 + c4);
        qs[r][c4] = a.x; qs[r][c4 + 1] = a.y; qs[r][c4 + 2] = a.z; qs[r][c4 + 3] = a.w;
        float4 b = *(const float4*)(kb + (size_t)r * 64 + c4);
        ks[r][c4] = b.x; ks[r][c4 + 1] = b.y; ks[r][c4 + 2] = b.z; ks[r][c4 + 3] = b.w;
    }
    __syncthreads();

    int tx = tid & 15, ty = tid >> 4;
    float acc[4][4];
#pragma unroll
    for (int i = 0; i < 4; i++)
#pragma unroll
        for (int j = 0; j < 4; j++) acc[i][j] = 0.0f;

#pragma unroll 8
    for (int d = 0; d < 64; d++) {
        float a[4], b[4];
#pragma unroll
        for (int i = 0; i < 4; i++) a[i] = qs[ty * 4 + i][d];
#pragma unroll
        for (int j = 0; j < 4; j++) b[j] = ks[tx * 4 + j][d];
#pragma unroll
        for (int i = 0; i < 4; i++)
#pragma unroll
            for (int j = 0; j < 4; j++) acc[i][j] += a[i] * b[j];
    }

    int q0 = qt * 64, k0 = kt * 64;
#pragma unroll
    for (int i = 0; i < 4; i++) {
        int qi = q0 + ty * 4 + i;
#pragma unroll
        for (int j = 0; j < 4; j++) {
            int kj = k0 + tx * 4 + j;
            if (kj <= qi)
                attn[((size_t)bh * Sn + qi) * Sn + kj] = acc[i][j] * SCALE_F;
        }
    }
}

// ---------------------------------------------------------------------------
// Row softmax, causal. One block per (bh, q) row. Masked region -> exact 0.
// ---------------------------------------------------------------------------
__device__ __forceinline__ float warpMax(float v) {
#pragma unroll
    for (int o = 16; o; o >>= 1) v = fmaxf(v, __shfl_xor_sync(0xffffffffu, v, o));
    return v;
}
__device__ __forceinline__ float warpSum(float v) {
#pragma unroll
    for (int o = 16; o; o >>= 1) v += __shfl_xor_sync(0xffffffffu, v, o);
    return v;
}

__global__ __launch_bounds__(256) void softmax_kernel(float* __restrict__ attn)
{
    size_t r = blockIdx.x;
    int qpos = (int)(r & (Sn - 1));
    float* row = attn + r * (size_t)Sn;
    int n = qpos + 1;
    int tid = threadIdx.x;
    int lane = tid & 31, wid = tid >> 5;

    __shared__ float sm[8];
    __shared__ float sres;

    float m = -1e30f;
    for (int c = tid; c < n; c += 256) m = fmaxf(m, row[c]);
    m = warpMax(m);
    if (lane == 0) sm[wid] = m;
    __syncthreads();
    if (tid < 32) {
        float x = (lane < 8) ? sm[lane] : -1e30f;
        x = warpMax(x);
        if (lane == 0) sres = x;
    }
    __syncthreads();
    m = sres;

    float s = 0.0f;
    for (int c = tid; c < n; c += 256) s += __expf(row[c] - m);
    s = warpSum(s);
    __syncthreads();
    if (lane == 0) sm[wid] = s;
    __syncthreads();
    if (tid < 32) {
        float x = (lane < 8) ? sm[lane] : 0.0f;
        x = warpSum(x);
        if (lane == 0) sres = x;
    }
    __syncthreads();
    float inv = 1.0f / sres;

    for (int c = tid; c < Sn; c += 256) {
        float v = (c < n) ? __expf(row[c] - m) * inv : 0.0f;
        row[c] = v;
    }
}

// ---------------------------------------------------------------------------
// ctx[b,h,qtile,:] = sum_{k<=q} attn * v ; output layout [B,S,H*DH]
// grid.x = 32 q-tiles, grid.y = bh
// ---------------------------------------------------------------------------
__global__ __launch_bounds__(256) void ctx_kernel(
    const float* __restrict__ attn, const float* __restrict__ v,
    float* __restrict__ ctx)
{
    int bh = blockIdx.y;
    int qt = blockIdx.x;
    int b = bh >> 4, h = bh & 15;

    __shared__ float at[64][65];
    __shared__ float vt[64][65];

    int tid = threadIdx.x;
    int tx = tid & 15, ty = tid >> 4;

    float acc[4][4];
#pragma unroll
    for (int i = 0; i < 4; i++)
#pragma unroll
        for (int j = 0; j < 4; j++) acc[i][j] = 0.0f;

    for (int kt = 0; kt <= qt; kt++) {
        for (int i = tid; i < 64 * 16; i += 256) {
            int r = i >> 4, c4 = (i & 15) * 4;
            float4 a = *(const float4*)(attn + ((size_t)bh * Sn + qt * 64 + r) * Sn + kt * 64 + c4);
            at[r][c4] = a.x; at[r][c4 + 1] = a.y; at[r][c4 + 2] = a.z; at[r][c4 + 3] = a.w;
            float4 w = *(const float4*)(v + ((size_t)bh * Sn + kt * 64 + r) * DHn + c4);
            vt[r][c4] = w.x; vt[r][c4 + 1] = w.y; vt[r][c4 + 2] = w.z; vt[r][c4 + 3] = w.w;
        }
        __syncthreads();

#pragma unroll 8
        for (int k2 = 0; k2 < 64; k2++) {
            float a[4], bb[4];
#pragma unroll
            for (int i = 0; i < 4; i++) a[i] = at[ty * 4 + i][k2];
#pragma unroll
            for (int j = 0; j < 4; j++) bb[j] = vt[k2][tx * 4 + j];
#pragma unroll
            for (int i = 0; i < 4; i++)
#pragma unroll
                for (int j = 0; j < 4; j++) acc[i][j] += a[i] * bb[j];
        }
        __syncthreads();
    }

#pragma unroll
    for (int i = 0; i < 4; i++) {
        int s = qt * 64 + ty * 4 + i;
#pragma unroll
        for (int j = 0; j < 4; j++) {
            int d = tx * 4 + j;
            ctx[((size_t)b * Sn + s) * Dn + h * DHn + d] = acc[i][j];
        }
    }
}

// ---------------------------------------------------------------------------
// Launch
// ---------------------------------------------------------------------------
extern "C" void kernel_launch(void* const* d_in, const int* in_sizes, int n_in,
                              void* d_out, int out_size)
{
    const float* Q  = (const float*)d_in[0];
    const float* K  = (const float*)d_in[1];
    const float* V  = (const float*)d_in[2];
    // d_in[3] = attention_mask (causal, hardcoded)
    const float* wq = (const float*)d_in[4];
    const float* bq = (const float*)d_in[5];
    const float* wk = (const float*)d_in[6];
    const float* bk = (const float*)d_in[7];
    const float* wv = (const float*)d_in[8];
    const float* bv = (const float*)d_in[9];
    const float* wo = (const float*)d_in[10];
    const float* bo = (const float*)d_in[11];

    float* out = (float*)d_out;

    float* attn;
    if ((size_t)out_size >= OUT_ELEMS + ATTN_ELEMS) {
        attn = out + OUT_ELEMS;   // tuple output: [out | attn]
    } else {
        void* p = nullptr;
        cudaGetSymbolAddress(&p, g_attn_scratch);
        attn = (float*)p;
    }

    float *gq, *gk, *gv, *gctx;
    {
        void* p;
        cudaGetSymbolAddress(&p, g_q);   gq   = (float*)p;
        cudaGetSymbolAddress(&p, g_k);   gk   = (float*)p;
        cudaGetSymbolAddress(&p, g_v);   gv   = (float*)p;
        cudaGetSymbolAddress(&p, g_ctx); gctx = (float*)p;
    }

    dim3 gemm_grid(Dn / 128, Mn / 128);   // (8, 64)

    sgemm_bias_kernel<<<gemm_grid, 256>>>(Q, wq, bq, gq, 1);
    sgemm_bias_kernel<<<gemm_grid, 256>>>(K, wk, bk, gk, 1);
    sgemm_bias_kernel<<<gemm_grid, 256>>>(V, wv, bv, gv, 1);

    scores_kernel<<<dim3(528, BHn), 256>>>(gq, gk, attn);
    softmax_kernel<<<BHn * Sn, 256>>>(attn);
    ctx_kernel<<<dim3(Sn / 64, BHn), 256>>>(attn, gv, gctx);

    sgemm_bias_kernel<<<gemm_grid, 256>>>(gctx, wo, bo, out, 0);
}

// round 3
// speedup vs baseline: 2.0652x; 2.0652x over previous
#include <cuda_runtime.h>
#include <cstdint>
#include <math.h>

// Problem constants
#define Bn   4
#define Sn   2048
#define Dn   1024
#define Hn   16
#define DHn  64
#define BHn  (Bn * Hn)          // 64
#define Mn   (Bn * Sn)          // 8192
#define SCALE_F 0.125f

#define OUT_ELEMS  ((size_t)Mn * Dn)            // 8,388,608
#define ATTN_ELEMS ((size_t)BHn * Sn * Sn)      // 268,435,456

// Scratch (device globals)
__device__ float g_q[Mn * Dn];            // [B,H,S,DH]
__device__ float g_k[Mn * Dn];
__device__ float g_v[Mn * Dn];
__device__ float g_ctx[Mn * Dn];          // [B,S,H*DH]
__device__ float g_attn_scratch[ATTN_ELEMS];

// ---------------------------------------------------------------------------
// tf32 helpers (standard PTX, works on plain compute_103)
// ---------------------------------------------------------------------------
__device__ __forceinline__ float f2tf32(float f) {
    uint32_t r; asm("cvt.rna.tf32.f32 %0, %1;" : "=r"(r) : "f"(f));
    return __uint_as_float(r);
}
__device__ __forceinline__ void mma_tf32(float c[4], const uint32_t a[4], const uint32_t b[2]) {
    asm volatile(
        "mma.sync.aligned.m16n8k8.row.col.f32.tf32.tf32.f32 "
        "{%0,%1,%2,%3}, {%4,%5,%6,%7}, {%8,%9}, {%0,%1,%2,%3};"
        : "+f"(c[0]), "+f"(c[1]), "+f"(c[2]), "+f"(c[3])
        : "r"(a[0]), "r"(a[1]), "r"(a[2]), "r"(a[3]), "r"(b[0]), "r"(b[1]));
}

// ---------------------------------------------------------------------------
// tf32 mma GEMM: out[M,N] = X[M,1024] @ W[1024,1024] + bias
// mode 0: row-major [M,N]; mode 1: head layout [B,H,S,DH]
// 256 threads, blocktile 128x128, BK=32, double-buffered dynamic smem.
// Warp grid 2(M) x 4(N); warp tile 64x32; mma m16n8k8.
// ---------------------------------------------------------------------------
#define AS_STRIDE 36
#define BS_STRIDE 132
#define ASZ (128 * AS_STRIDE)      // floats
#define BSZ (32 * BS_STRIDE)
#define GEMM_SMEM ((2 * ASZ + 2 * BSZ) * 4)   // 70656 bytes

__global__ __launch_bounds__(256, 1) void tf32_gemm_kernel(
    const float* __restrict__ X, const float* __restrict__ W,
    const float* __restrict__ bias, float* __restrict__ out, int mode)
{
    extern __shared__ float sm[];
    float* Asm[2] = { sm, sm + ASZ };
    float* Bsm[2] = { sm + 2 * ASZ, sm + 2 * ASZ + BSZ };

    const int tid = threadIdx.x;
    const int wid = tid >> 5, lane = tid & 31;
    const int g = lane >> 2, t = lane & 3;
    const int warpM = wid & 1, warpN = wid >> 1;
    const int bm = blockIdx.y * 128, bn = blockIdx.x * 128;

    float c[4][4][4];
#pragma unroll
    for (int i = 0; i < 4; i++)
#pragma unroll
        for (int j = 0; j < 4; j++)
#pragma unroll
            for (int k = 0; k < 4; k++) c[i][j][k] = 0.0f;

    float4 ra[4], rb[4];

    // ---- stage 0 direct to smem buf 0 ----
    {
        const float* Xp = X + (size_t)bm * Dn;
        const float* Wp = W + bn;
#pragma unroll
        for (int j = 0; j < 4; j++) {
            int ia = tid + j * 256;
            float4 a = *(const float4*)(Xp + (size_t)(ia >> 3) * Dn + (ia & 7) * 4);
            float* pa = Asm[0] + (ia >> 3) * AS_STRIDE + (ia & 7) * 4;
            pa[0] = f2tf32(a.x); pa[1] = f2tf32(a.y); pa[2] = f2tf32(a.z); pa[3] = f2tf32(a.w);
            float4 b = *(const float4*)(Wp + (size_t)(ia >> 5) * Dn + (ia & 31) * 4);
            float* pb = Bsm[0] + (ia >> 5) * BS_STRIDE + (ia & 31) * 4;
            pb[0] = f2tf32(b.x); pb[1] = f2tf32(b.y); pb[2] = f2tf32(b.z); pb[3] = f2tf32(b.w);
        }
    }
    __syncthreads();

    const int NSTAGE = Dn / 32;   // 32
    for (int s = 0; s < NSTAGE; s++) {
        int cur = s & 1;
        if (s + 1 < NSTAGE) {
            const float* Xp = X + (size_t)bm * Dn + (s + 1) * 32;
            const float* Wp = W + (size_t)(s + 1) * 32 * Dn + bn;
#pragma unroll
            for (int j = 0; j < 4; j++) {
                int ia = tid + j * 256;
                ra[j] = *(const float4*)(Xp + (size_t)(ia >> 3) * Dn + (ia & 7) * 4);
                rb[j] = *(const float4*)(Wp + (size_t)(ia >> 5) * Dn + (ia & 31) * 4);
            }
        }

        const float* A = Asm[cur];
        const float* B = Bsm[cur];
#pragma unroll
        for (int kk = 0; kk < 32; kk += 8) {
            uint32_t af[4][4], bf[4][2];
#pragma unroll
            for (int mt = 0; mt < 4; mt++) {
                int r0 = warpM * 64 + mt * 16 + g;
                af[mt][0] = __float_as_uint(A[r0 * AS_STRIDE + kk + t]);
                af[mt][1] = __float_as_uint(A[(r0 + 8) * AS_STRIDE + kk + t]);
                af[mt][2] = __float_as_uint(A[r0 * AS_STRIDE + kk + t + 4]);
                af[mt][3] = __float_as_uint(A[(r0 + 8) * AS_STRIDE + kk + t + 4]);
            }
#pragma unroll
            for (int nt = 0; nt < 4; nt++) {
                int n0 = warpN * 32 + nt * 8 + g;
                bf[nt][0] = __float_as_uint(B[(kk + t) * BS_STRIDE + n0]);
                bf[nt][1] = __float_as_uint(B[(kk + t + 4) * BS_STRIDE + n0]);
            }
#pragma unroll
            for (int mt = 0; mt < 4; mt++)
#pragma unroll
                for (int nt = 0; nt < 4; nt++)
                    mma_tf32(c[mt][nt], af[mt], bf[nt]);
        }

        if (s + 1 < NSTAGE) {
            float* Ab = Asm[1 - cur];
            float* Bb = Bsm[1 - cur];
#pragma unroll
            for (int j = 0; j < 4; j++) {
                int ia = tid + j * 256;
                float* pa = Ab + (ia >> 3) * AS_STRIDE + (ia & 7) * 4;
                pa[0] = f2tf32(ra[j].x); pa[1] = f2tf32(ra[j].y);
                pa[2] = f2tf32(ra[j].z); pa[3] = f2tf32(ra[j].w);
                float* pb = Bb + (ia >> 5) * BS_STRIDE + (ia & 31) * 4;
                pb[0] = f2tf32(rb[j].x); pb[1] = f2tf32(rb[j].y);
                pb[2] = f2tf32(rb[j].z); pb[3] = f2tf32(rb[j].w);
            }
        }
        __syncthreads();
    }

    // epilogue
#pragma unroll
    for (int mt = 0; mt < 4; mt++) {
#pragma unroll
        for (int nt = 0; nt < 4; nt++) {
            int m0 = bm + warpM * 64 + mt * 16 + g;
            int n0 = bn + warpN * 32 + nt * 8 + 2 * t;
#pragma unroll
            for (int half = 0; half < 2; half++) {
                int m = m0 + half * 8;
                float v0 = c[mt][nt][half * 2 + 0] + bias[n0];
                float v1 = c[mt][nt][half * 2 + 1] + bias[n0 + 1];
                if (mode == 0) {
                    out[(size_t)m * Dn + n0] = v0;
                    out[(size_t)m * Dn + n0 + 1] = v1;
                } else {
                    int b = m >> 11, sq = m & (Sn - 1);
                    int h = n0 >> 6, d = n0 & 63;
                    size_t base = (((size_t)b * Hn + h) * Sn + sq) * DHn + d;
                    out[base] = v0;
                    out[base + 1] = v1;
                }
            }
        }
    }
}

// ---------------------------------------------------------------------------
// Scores via mma: lower-tri 128x128 tiles, S = q @ k^T * SCALE. grid (136, 64)
// Warp grid 2(q) x 4(k); warp tile 64x32.
// ---------------------------------------------------------------------------
__global__ __launch_bounds__(256, 1) void scores_kernel(
    const float* __restrict__ q, const float* __restrict__ k,
    float* __restrict__ attn)
{
    __shared__ float Qs[128][AS_STRIDE];
    __shared__ float Ks[128][AS_STRIDE];

    const int bh = blockIdx.y;
    int tt = blockIdx.x;
    int qt = (int)floorf((sqrtf(8.0f * (float)tt + 1.0f) - 1.0f) * 0.5f);
    while ((qt + 1) * (qt + 2) / 2 <= tt) ++qt;
    while (qt * (qt + 1) / 2 > tt) --qt;
    const int kt = tt - qt * (qt + 1) / 2;

    const float* qb = q + ((size_t)bh * Sn + qt * 128) * DHn;
    const float* kb = k + ((size_t)bh * Sn + kt * 128) * DHn;

    const int tid = threadIdx.x;
    const int wid = tid >> 5, lane = tid & 31;
    const int g = lane >> 2, t = lane & 3;
    const int warpM = wid & 1, warpN = wid >> 1;

    float c[4][4][4];
#pragma unroll
    for (int i = 0; i < 4; i++)
#pragma unroll
        for (int j = 0; j < 4; j++)
#pragma unroll
            for (int kk = 0; kk < 4; kk++) c[i][j][kk] = 0.0f;

    for (int stage = 0; stage < 2; stage++) {   // DH=64 in two 32-chunks
        int k0 = stage * 32;
#pragma unroll
        for (int j = 0; j < 4; j++) {
            int ia = tid + j * 256;
            int row = ia >> 3, cc = (ia & 7) * 4;
            float4 a = *(const float4*)(qb + (size_t)row * DHn + k0 + cc);
            Qs[row][cc] = f2tf32(a.x); Qs[row][cc + 1] = f2tf32(a.y);
            Qs[row][cc + 2] = f2tf32(a.z); Qs[row][cc + 3] = f2tf32(a.w);
            float4 b = *(const float4*)(kb + (size_t)row * DHn + k0 + cc);
            Ks[row][cc] = f2tf32(b.x); Ks[row][cc + 1] = f2tf32(b.y);
            Ks[row][cc + 2] = f2tf32(b.z); Ks[row][cc + 3] = f2tf32(b.w);
        }
        __syncthreads();

#pragma unroll
        for (int kk = 0; kk < 32; kk += 8) {
            uint32_t af[4][4], bf[4][2];
#pragma unroll
            for (int mt = 0; mt < 4; mt++) {
                int r0 = warpM * 64 + mt * 16 + g;
                af[mt][0] = __float_as_uint(Qs[r0][kk + t]);
                af[mt][1] = __float_as_uint(Qs[r0 + 8][kk + t]);
                af[mt][2] = __float_as_uint(Qs[r0][kk + t + 4]);
                af[mt][3] = __float_as_uint(Qs[r0 + 8][kk + t + 4]);
            }
#pragma unroll
            for (int nt = 0; nt < 4; nt++) {
                int n0 = warpN * 32 + nt * 8 + g;
                bf[nt][0] = __float_as_uint(Ks[n0][kk + t]);
                bf[nt][1] = __float_as_uint(Ks[n0][kk + t + 4]);
            }
#pragma unroll
            for (int mt = 0; mt < 4; mt++)
#pragma unroll
                for (int nt = 0; nt < 4; nt++)
                    mma_tf32(c[mt][nt], af[mt], bf[nt]);
        }
        __syncthreads();
    }

    const int q0 = qt * 128, kk0 = kt * 128;
    const bool diag = (qt == kt);
#pragma unroll
    for (int mt = 0; mt < 4; mt++) {
#pragma unroll
        for (int nt = 0; nt < 4; nt++) {
            int qi0 = q0 + warpM * 64 + mt * 16 + g;
            int kj = kk0 + warpN * 32 + nt * 8 + 2 * t;
#pragma unroll
            for (int half = 0; half < 2; half++) {
                int qi = qi0 + half * 8;
                float* row = attn + ((size_t)bh * Sn + qi) * Sn;
                float v0 = c[mt][nt][half * 2 + 0] * SCALE_F;
                float v1 = c[mt][nt][half * 2 + 1] * SCALE_F;
                if (!diag || kj <= qi)     row[kj] = v0;
                if (!diag || kj + 1 <= qi) row[kj + 1] = v1;
            }
        }
    }
}

// ---------------------------------------------------------------------------
// Row softmax, causal (masked tail -> exact 0)
// ---------------------------------------------------------------------------
__device__ __forceinline__ float warpMax(float v) {
#pragma unroll
    for (int o = 16; o; o >>= 1) v = fmaxf(v, __shfl_xor_sync(0xffffffffu, v, o));
    return v;
}
__device__ __forceinline__ float warpSum(float v) {
#pragma unroll
    for (int o = 16; o; o >>= 1) v += __shfl_xor_sync(0xffffffffu, v, o);
    return v;
}

__global__ __launch_bounds__(256) void softmax_kernel(float* __restrict__ attn)
{
    size_t r = blockIdx.x;
    int qpos = (int)(r & (Sn - 1));
    float* row = attn + r * (size_t)Sn;
    int n = qpos + 1;
    int tid = threadIdx.x;
    int lane = tid & 31, wid = tid >> 5;

    __shared__ float sm[8];
    __shared__ float sres;

    float m = -1e30f;
    for (int c = tid; c < n; c += 256) m = fmaxf(m, row[c]);
    m = warpMax(m);
    if (lane == 0) sm[wid] = m;
    __syncthreads();
    if (tid < 32) {
        float x = (lane < 8) ? sm[lane] : -1e30f;
        x = warpMax(x);
        if (lane == 0) sres = x;
    }
    __syncthreads();
    m = sres;

    float s = 0.0f;
    for (int c = tid; c < n; c += 256) s += __expf(row[c] - m);
    s = warpSum(s);
    __syncthreads();
    if (lane == 0) sm[wid] = s;
    __syncthreads();
    if (tid < 32) {
        float x = (lane < 8) ? sm[lane] : 0.0f;
        x = warpSum(x);
        if (lane == 0) sres = x;
    }
    __syncthreads();
    float inv = 1.0f / sres;

    for (int c = tid; c < Sn; c += 256) {
        float v = (c < n) ? __expf(row[c] - m) * inv : 0.0f;
        row[c] = v;
    }
}

// ---------------------------------------------------------------------------
// ctx = attn @ v via mma. grid (16, 64): q-tile 128, d=64 per CTA.
// Warp grid 4(q) x 2(d); warp tile 32x32. k-chunks of 32.
// ---------------------------------------------------------------------------
#define VS_STRIDE 68
__global__ __launch_bounds__(256, 1) void ctx_kernel(
    const float* __restrict__ attn, const float* __restrict__ v,
    float* __restrict__ ctx)
{
    __shared__ float Ps[128][AS_STRIDE];
    __shared__ float Vs[32][VS_STRIDE];

    const int bh = blockIdx.y;
    const int qt = blockIdx.x;
    const int b = bh >> 4, h = bh & 15;

    const int tid = threadIdx.x;
    const int wid = tid >> 5, lane = tid & 31;
    const int g = lane >> 2, t = lane & 3;
    const int warpM = wid >> 1, warpN = wid & 1;

    float c[2][4][4];
#pragma unroll
    for (int i = 0; i < 2; i++)
#pragma unroll
        for (int j = 0; j < 4; j++)
#pragma unroll
            for (int kk = 0; kk < 4; kk++) c[i][j][kk] = 0.0f;

    const float* pbase = attn + ((size_t)bh * Sn + qt * 128) * Sn;
    const float* vbase = v + (size_t)bh * Sn * DHn;

    const int nchunks = (qt + 1) * 4;
    for (int ch = 0; ch < nchunks; ch++) {
        int kbase = ch * 32;
#pragma unroll
        for (int j = 0; j < 4; j++) {
            int ia = tid + j * 256;
            int row = ia >> 3, cc = (ia & 7) * 4;
            float4 a = *(const float4*)(pbase + (size_t)row * Sn + kbase + cc);
            Ps[row][cc] = f2tf32(a.x); Ps[row][cc + 1] = f2tf32(a.y);
            Ps[row][cc + 2] = f2tf32(a.z); Ps[row][cc + 3] = f2tf32(a.w);
        }
#pragma unroll
        for (int j = 0; j < 2; j++) {
            int ia = tid + j * 256;
            int row = ia >> 4, cc = (ia & 15) * 4;
            float4 w = *(const float4*)(vbase + (size_t)(kbase + row) * DHn + cc);
            Vs[row][cc] = f2tf32(w.x); Vs[row][cc + 1] = f2tf32(w.y);
            Vs[row][cc + 2] = f2tf32(w.z); Vs[row][cc + 3] = f2tf32(w.w);
        }
        __syncthreads();

#pragma unroll
        for (int kk = 0; kk < 32; kk += 8) {
            uint32_t af[2][4], bf[4][2];
#pragma unroll
            for (int mt = 0; mt < 2; mt++) {
                int r0 = warpM * 32 + mt * 16 + g;
                af[mt][0] = __float_as_uint(Ps[r0][kk + t]);
                af[mt][1] = __float_as_uint(Ps[r0 + 8][kk + t]);
                af[mt][2] = __float_as_uint(Ps[r0][kk + t + 4]);
                af[mt][3] = __float_as_uint(Ps[r0 + 8][kk + t + 4]);
            }
#pragma unroll
            for (int nt = 0; nt < 4; nt++) {
                int n0 = warpN * 32 + nt * 8 + g;
                bf[nt][0] = __float_as_uint(Vs[kk + t][n0]);
                bf[nt][1] = __float_as_uint(Vs[kk + t + 4][n0]);
            }
#pragma unroll
            for (int mt = 0; mt < 2; mt++)
#pragma unroll
                for (int nt = 0; nt < 4; nt++)
                    mma_tf32(c[mt][nt], af[mt], bf[nt]);
        }
        __syncthreads();
    }

#pragma unroll
    for (int mt = 0; mt < 2; mt++) {
#pragma unroll
        for (int nt = 0; nt < 4; nt++) {
            int s0 = qt * 128 + warpM * 32 + mt * 16 + g;
            int d0 = warpN * 32 + nt * 8 + 2 * t;
#pragma unroll
            for (int half = 0; half < 2; half++) {
                int s = s0 + half * 8;
                size_t base = ((size_t)b * Sn + s) * Dn + h * DHn + d0;
                ctx[base] = c[mt][nt][half * 2 + 0];
                ctx[base + 1] = c[mt][nt][half * 2 + 1];
            }
        }
    }
}

// ---------------------------------------------------------------------------
// Launch
// ---------------------------------------------------------------------------
extern "C" void kernel_launch(void* const* d_in, const int* in_sizes, int n_in,
                              void* d_out, int out_size)
{
    const float* Q  = (const float*)d_in[0];
    const float* K  = (const float*)d_in[1];
    const float* V  = (const float*)d_in[2];
    const float* wq = (const float*)d_in[4];
    const float* bq = (const float*)d_in[5];
    const float* wk = (const float*)d_in[6];
    const float* bk = (const float*)d_in[7];
    const float* wv = (const float*)d_in[8];
    const float* bv = (const float*)d_in[9];
    const float* wo = (const float*)d_in[10];
    const float* bo = (const float*)d_in[11];

    float* out = (float*)d_out;

    float* attn;
    if ((size_t)out_size >= OUT_ELEMS + ATTN_ELEMS) {
        attn = out + OUT_ELEMS;
    } else {
        void* p = nullptr;
        cudaGetSymbolAddress(&p, g_attn_scratch);
        attn = (float*)p;
    }

    float *gq, *gk, *gv, *gctx;
    {
        void* p;
        cudaGetSymbolAddress(&p, g_q);   gq   = (float*)p;
        cudaGetSymbolAddress(&p, g_k);   gk   = (float*)p;
        cudaGetSymbolAddress(&p, g_v);   gv   = (float*)p;
        cudaGetSymbolAddress(&p, g_ctx); gctx = (float*)p;
    }

    cudaFuncSetAttribute(tf32_gemm_kernel,
                         cudaFuncAttributeMaxDynamicSharedMemorySize, GEMM_SMEM);

    dim3 gg(Dn / 128, Mn / 128);   // (8, 64)
    tf32_gemm_kernel<<<gg, 256, GEMM_SMEM>>>(Q, wq, bq, gq, 1);
    tf32_gemm_kernel<<<gg, 256, GEMM_SMEM>>>(K, wk, bk, gk, 1);
    tf32_gemm_kernel<<<gg, 256, GEMM_SMEM>>>(V, wv, bv, gv, 1);

    scores_kernel<<<dim3(136, BHn), 256>>>(gq, gk, attn);
    softmax_kernel<<<BHn * Sn, 256>>>(attn);
    ctx_kernel<<<dim3(Sn / 128, BHn), 256>>>(attn, gv, gctx);

    tf32_gemm_kernel<<<gg, 256, GEMM_SMEM>>>(gctx, wo, bo, out, 0);
}

// round 4
// speedup vs baseline: 3.0099x; 1.4574x over previous
#include <cuda_runtime.h>
#include <cstdint>
#include <math.h>

// Problem constants
#define Bn   4
#define Sn   2048
#define Dn   1024
#define Hn   16
#define DHn  64
#define BHn  (Bn * Hn)          // 64
#define Mn   (Bn * Sn)          // 8192
#define NQT  (Sn / 128)         // 16 q-tiles
#define SCALE_F 0.125f

#define OUT_ELEMS  ((size_t)Mn * Dn)            // 8,388,608
#define ATTN_ELEMS ((size_t)BHn * Sn * Sn)      // 268,435,456

// Scratch (device globals)
__device__ float g_q[Mn * Dn];            // [B,H,S,DH]
__device__ float g_k[Mn * Dn];
__device__ float g_v[Mn * Dn];
__device__ float g_ctx[Mn * Dn];          // [B,S,H*DH]
__device__ float g_attn_scratch[ATTN_ELEMS];

// ---------------------------------------------------------------------------
// PTX helpers (all standard, compile for bare compute_103)
// ---------------------------------------------------------------------------
__device__ __forceinline__ uint32_t smem_u32(const void* p) {
    uint32_t a;
    asm("{ .reg .u64 t; cvta.to.shared.u64 t, %1; cvt.u32.u64 %0, t; }" : "=r"(a) : "l"(p));
    return a;
}
#define CP16(dst, src) \
    asm volatile("cp.async.cg.shared.global [%0], [%1], 16;" :: "r"(dst), "l"(src))
#define CP_COMMIT() asm volatile("cp.async.commit_group;")
#define CP_WAIT1()  asm volatile("cp.async.wait_group 1;")
#define CP_WAIT0()  asm volatile("cp.async.wait_group 0;")

__device__ __forceinline__ uint32_t tf32b(float f) {
    uint32_t r; asm("cvt.rna.tf32.f32 %0, %1;" : "=r"(r) : "f"(f));
    return r;
}
__device__ __forceinline__ void mma_tf32(float c[4], const uint32_t a[4], const uint32_t b[2]) {
    asm volatile(
        "mma.sync.aligned.m16n8k8.row.col.f32.tf32.tf32.f32 "
        "{%0,%1,%2,%3}, {%4,%5,%6,%7}, {%8,%9}, {%0,%1,%2,%3};"
        : "+f"(c[0]), "+f"(c[1]), "+f"(c[2]), "+f"(c[3])
        : "r"(a[0]), "r"(a[1]), "r"(a[2]), "r"(a[3]), "r"(b[0]), "r"(b[1]));
}

// ---------------------------------------------------------------------------
// tf32 mma GEMM: out[M,N] = X[M,1024] @ W[1024,1024] + bias
// 256 threads, blocktile 128x128, BK=32, 3-stage cp.async pipeline.
// Warp grid 2(M) x 4(N); warp tile 64x32.
// smem per stage: A 128x36 (18432B) + B 32x132 (16896B) = 35328B; x3 = 105984B
// ---------------------------------------------------------------------------
#define G_AST 36
#define G_BST 132
#define G_STAGE_F (128 * G_AST + 32 * G_BST)      // floats per stage = 8832
#define GEMM_SMEM (3 * G_STAGE_F * 4)             // 105984 bytes

__global__ __launch_bounds__(256) void tf32_gemm_kernel(
    const float* __restrict__ X, const float* __restrict__ W,
    const float* __restrict__ bias, float* __restrict__ out, int mode)
{
    extern __shared__ float sm[];
    const int tid = threadIdx.x;
    const int wid = tid >> 5, lane = tid & 31;
    const int g = lane >> 2, t = lane & 3;
    const int warpM = wid & 1, warpN = wid >> 1;
    const int bm = blockIdx.y * 128, bn = blockIdx.x * 128;

    const uint32_t sbase = smem_u32(sm);

    float c[4][4][4];
#pragma unroll
    for (int i = 0; i < 4; i++)
#pragma unroll
        for (int j = 0; j < 4; j++)
#pragma unroll
            for (int k = 0; k < 4; k++) c[i][j][k] = 0.0f;

    // cp.async issue for chunk cidx into stage buf
    auto issue = [&](int cidx, int buf) {
        const float* Xp = X + (size_t)bm * Dn + cidx * 32;
        const float* Wp = W + (size_t)(cidx * 32) * Dn + bn;
        uint32_t abase = sbase + buf * (G_STAGE_F * 4);
        uint32_t bbase = abase + 128 * G_AST * 4;
#pragma unroll
        for (int j = 0; j < 4; j++) {
            int ia = tid + j * 256;
            int ar = ia >> 3, ac = ia & 7;
            CP16(abase + ar * (G_AST * 4) + ac * 16, Xp + (size_t)ar * Dn + ac * 4);
            int br = ia >> 5, bc = ia & 31;
            CP16(bbase + br * (G_BST * 4) + bc * 16, Wp + (size_t)br * Dn + bc * 4);
        }
    };

    issue(0, 0); CP_COMMIT();
    issue(1, 1); CP_COMMIT();

    const int NCH = Dn / 32;   // 32
    for (int s = 0; s < NCH; s++) {
        int buf = s % 3;
        if (s < NCH - 2) CP_WAIT1(); else CP_WAIT0();
        __syncthreads();
        if (s + 2 < NCH) { issue(s + 2, (s + 2) % 3); CP_COMMIT(); }

        const float* A = sm + buf * G_STAGE_F;
        const float* B = A + 128 * G_AST;
#pragma unroll
        for (int kk = 0; kk < 32; kk += 8) {
            uint32_t af[4][4], bf[4][2];
#pragma unroll
            for (int mt = 0; mt < 4; mt++) {
                int r0 = warpM * 64 + mt * 16 + g;
                af[mt][0] = tf32b(A[r0 * G_AST + kk + t]);
                af[mt][1] = tf32b(A[(r0 + 8) * G_AST + kk + t]);
                af[mt][2] = tf32b(A[r0 * G_AST + kk + t + 4]);
                af[mt][3] = tf32b(A[(r0 + 8) * G_AST + kk + t + 4]);
            }
#pragma unroll
            for (int nt = 0; nt < 4; nt++) {
                int n0 = warpN * 32 + nt * 8 + g;
                bf[nt][0] = tf32b(B[(kk + t) * G_BST + n0]);
                bf[nt][1] = tf32b(B[(kk + t + 4) * G_BST + n0]);
            }
#pragma unroll
            for (int mt = 0; mt < 4; mt++)
#pragma unroll
                for (int nt = 0; nt < 4; nt++)
                    mma_tf32(c[mt][nt], af[mt], bf[nt]);
        }
    }

    // epilogue
#pragma unroll
    for (int mt = 0; mt < 4; mt++) {
#pragma unroll
        for (int nt = 0; nt < 4; nt++) {
            int m0 = bm + warpM * 64 + mt * 16 + g;
            int n0 = bn + warpN * 32 + nt * 8 + 2 * t;
#pragma unroll
            for (int half = 0; half < 2; half++) {
                int m = m0 + half * 8;
                float v0 = c[mt][nt][half * 2 + 0] + bias[n0];
                float v1 = c[mt][nt][half * 2 + 1] + bias[n0 + 1];
                if (mode == 0) {
                    out[(size_t)m * Dn + n0] = v0;
                    out[(size_t)m * Dn + n0 + 1] = v1;
                } else {
                    int b = m >> 11, sq = m & (Sn - 1);
                    int h = n0 >> 6, d = n0 & 63;
                    size_t base = (((size_t)b * Hn + h) * Sn + sq) * DHn + d;
                    out[base] = v0;
                    out[base + 1] = v1;
                }
            }
        }
    }
}

// ---------------------------------------------------------------------------
// Scores: grid (NQT, BHn); CTA owns q-tile (128 rows), loops kt=0..qt.
// Q resident in smem; K double-buffered via cp.async.
// smem: Q 128x68 (34816B) + 2x K 128x68 = 104448B
// ---------------------------------------------------------------------------
#define S_ST 68
#define S_QF (128 * S_ST)
#define SCORES_SMEM ((S_QF + 2 * S_QF) * 4)   // 104448 bytes

__global__ __launch_bounds__(256) void scores_kernel(
    const float* __restrict__ q, const float* __restrict__ k,
    float* __restrict__ attn)
{
    extern __shared__ float sm[];
    float* Qs = sm;
    float* Ks[2] = { sm + S_QF, sm + 2 * S_QF };

    const int bh = blockIdx.y;
    const int qt = (NQT - 1) - blockIdx.x;   // heavy tiles first
    const int tid = threadIdx.x;
    const int wid = tid >> 5, lane = tid & 31;
    const int g = lane >> 2, t = lane & 3;
    const int warpM = wid & 1, warpN = wid >> 1;

    const uint32_t sbase = smem_u32(sm);
    const float* qb = q + ((size_t)bh * Sn + qt * 128) * DHn;
    const float* kbase = k + (size_t)bh * Sn * DHn;

    // load Q (128x64) once
    {
        uint32_t qdst = sbase;
#pragma unroll
        for (int j = 0; j < 8; j++) {
            int ia = tid + j * 256;
            int r = ia >> 4, c4 = ia & 15;
            CP16(qdst + r * (S_ST * 4) + c4 * 16, qb + (size_t)r * DHn + c4 * 4);
        }
        CP_COMMIT();
    }
    auto issueK = [&](int kt, int buf) {
        const float* kb = kbase + (size_t)(kt * 128) * DHn;
        uint32_t kdst = sbase + (1 + buf) * (S_QF * 4);
#pragma unroll
        for (int j = 0; j < 8; j++) {
            int ia = tid + j * 256;
            int r = ia >> 4, c4 = ia & 15;
            CP16(kdst + r * (S_ST * 4) + c4 * 16, kb + (size_t)r * DHn + c4 * 4);
        }
    };
    issueK(0, 0); CP_COMMIT();

    for (int kt = 0; kt <= qt; kt++) {
        CP_WAIT0();
        __syncthreads();
        if (kt < qt) { issueK(kt + 1, (kt + 1) & 1); CP_COMMIT(); }

        const float* K = Ks[kt & 1];
        float c[4][4][4];
#pragma unroll
        for (int i = 0; i < 4; i++)
#pragma unroll
            for (int j = 0; j < 4; j++)
#pragma unroll
                for (int kk = 0; kk < 4; kk++) c[i][j][kk] = 0.0f;

#pragma unroll
        for (int kk = 0; kk < 64; kk += 8) {
            uint32_t af[4][4], bf[4][2];
#pragma unroll
            for (int mt = 0; mt < 4; mt++) {
                int r0 = warpM * 64 + mt * 16 + g;
                af[mt][0] = tf32b(Qs[r0 * S_ST + kk + t]);
                af[mt][1] = tf32b(Qs[(r0 + 8) * S_ST + kk + t]);
                af[mt][2] = tf32b(Qs[r0 * S_ST + kk + t + 4]);
                af[mt][3] = tf32b(Qs[(r0 + 8) * S_ST + kk + t + 4]);
            }
#pragma unroll
            for (int nt = 0; nt < 4; nt++) {
                int n0 = warpN * 32 + nt * 8 + g;
                bf[nt][0] = tf32b(K[n0 * S_ST + kk + t]);
                bf[nt][1] = tf32b(K[n0 * S_ST + kk + t + 4]);
            }
#pragma unroll
            for (int mt = 0; mt < 4; mt++)
#pragma unroll
                for (int nt = 0; nt < 4; nt++)
                    mma_tf32(c[mt][nt], af[mt], bf[nt]);
        }

        const int q0 = qt * 128, kk0 = kt * 128;
        const bool diag = (qt == kt);
#pragma unroll
        for (int mt = 0; mt < 4; mt++) {
#pragma unroll
            for (int nt = 0; nt < 4; nt++) {
                int qi0 = q0 + warpM * 64 + mt * 16 + g;
                int kj = kk0 + warpN * 32 + nt * 8 + 2 * t;
#pragma unroll
                for (int half = 0; half < 2; half++) {
                    int qi = qi0 + half * 8;
                    float* row = attn + ((size_t)bh * Sn + qi) * Sn;
                    float v0 = c[mt][nt][half * 2 + 0] * SCALE_F;
                    float v1 = c[mt][nt][half * 2 + 1] * SCALE_F;
                    if (!diag || kj <= qi)     row[kj] = v0;
                    if (!diag || kj + 1 <= qi) row[kj + 1] = v1;
                }
            }
        }
        __syncthreads();
    }
}

// ---------------------------------------------------------------------------
// Row softmax, causal; row cached in smem, one gmem read + one write.
// ---------------------------------------------------------------------------
__device__ __forceinline__ float warpMax(float v) {
#pragma unroll
    for (int o = 16; o; o >>= 1) v = fmaxf(v, __shfl_xor_sync(0xffffffffu, v, o));
    return v;
}
__device__ __forceinline__ float warpSum(float v) {
#pragma unroll
    for (int o = 16; o; o >>= 1) v += __shfl_xor_sync(0xffffffffu, v, o);
    return v;
}

__global__ __launch_bounds__(256) void softmax_kernel(float* __restrict__ attn)
{
    __shared__ float buf[Sn];
    __shared__ float red[8];
    __shared__ float rres;

    size_t r = blockIdx.x;
    int qpos = (int)(r & (Sn - 1));
    float* row = attn + r * (size_t)Sn;
    int n = qpos + 1;
    int tid = threadIdx.x;
    int lane = tid & 31, wid = tid >> 5;

    // load [0, n) into smem
    int n4 = n >> 2;
    for (int i = tid; i < n4; i += 256)
        *(float4*)&buf[i * 4] = *(const float4*)&row[i * 4];
    for (int c = n4 * 4 + tid; c < n; c += 256)
        buf[c] = row[c];
    __syncthreads();

    float m = -1e30f;
    for (int c = tid; c < n; c += 256) m = fmaxf(m, buf[c]);
    m = warpMax(m);
    if (lane == 0) red[wid] = m;
    __syncthreads();
    if (tid < 32) {
        float x = (lane < 8) ? red[lane] : -1e30f;
        x = warpMax(x);
        if (lane == 0) rres = x;
    }
    __syncthreads();
    m = rres;

    float s = 0.0f;
    for (int c = tid; c < n; c += 256) {
        float e = __expf(buf[c] - m);
        buf[c] = e;
        s += e;
    }
    s = warpSum(s);
    __syncthreads();
    if (lane == 0) red[wid] = s;
    __syncthreads();
    if (tid < 32) {
        float x = (lane < 8) ? red[lane] : 0.0f;
        x = warpSum(x);
        if (lane == 0) rres = x;
    }
    __syncthreads();
    float inv = 1.0f / rres;

    for (int i = tid; i < Sn / 4; i += 256) {
        int c = i * 4;
        float4 o;
        o.x = (c + 0 < n) ? buf[c + 0] * inv : 0.0f;
        o.y = (c + 1 < n) ? buf[c + 1] * inv : 0.0f;
        o.z = (c + 2 < n) ? buf[c + 2] * inv : 0.0f;
        o.w = (c + 3 < n) ? buf[c + 3] * inv : 0.0f;
        *(float4*)&row[c] = o;
    }
}

// ---------------------------------------------------------------------------
// ctx = attn @ v via mma, double-buffered cp.async. grid (NQT, BHn).
// Warp grid 4(q) x 2(d); warp tile 32x32; k-chunks of 32.
// smem per stage: P 128x36 (18432B) + V 32x68 (8704B) = 27136B; x2 = 54272B
// ---------------------------------------------------------------------------
#define C_PST 36
#define C_VST 68
#define C_STAGE_F (128 * C_PST + 32 * C_VST)   // 6784 floats
#define CTX_SMEM (2 * C_STAGE_F * 4)           // 54272 bytes

__global__ __launch_bounds__(256) void ctx_kernel(
    const float* __restrict__ attn, const float* __restrict__ v,
    float* __restrict__ ctx)
{
    extern __shared__ float sm[];
    const int bh = blockIdx.y;
    const int qt = (NQT - 1) - blockIdx.x;
    const int b = bh >> 4, h = bh & 15;

    const int tid = threadIdx.x;
    const int wid = tid >> 5, lane = tid & 31;
    const int g = lane >> 2, t = lane & 3;
    const int warpM = wid >> 1, warpN = wid & 1;

    const uint32_t sbase = smem_u32(sm);
    const float* pbase = attn + ((size_t)bh * Sn + qt * 128) * Sn;
    const float* vbase = v + (size_t)bh * Sn * DHn;

    float c[2][4][4];
#pragma unroll
    for (int i = 0; i < 2; i++)
#pragma unroll
        for (int j = 0; j < 4; j++)
#pragma unroll
            for (int kk = 0; kk < 4; kk++) c[i][j][kk] = 0.0f;

    auto issue = [&](int ch, int buf) {
        int kb = ch * 32;
        uint32_t pdst = sbase + buf * (C_STAGE_F * 4);
        uint32_t vdst = pdst + 128 * C_PST * 4;
#pragma unroll
        for (int j = 0; j < 4; j++) {
            int ia = tid + j * 256;
            int r = ia >> 3, c4 = ia & 7;
            CP16(pdst + r * (C_PST * 4) + c4 * 16, pbase + (size_t)r * Sn + kb + c4 * 4);
        }
#pragma unroll
        for (int j = 0; j < 2; j++) {
            int ia = tid + j * 256;
            int r = ia >> 4, c4 = ia & 15;
            CP16(vdst + r * (C_VST * 4) + c4 * 16, vbase + (size_t)(kb + r) * DHn + c4 * 4);
        }
    };

    const int nchunks = (qt + 1) * 4;
    issue(0, 0); CP_COMMIT();

    for (int ch = 0; ch < nchunks; ch++) {
        CP_WAIT0();
        __syncthreads();
        if (ch + 1 < nchunks) { issue(ch + 1, (ch + 1) & 1); CP_COMMIT(); }

        const float* P = sm + (ch & 1) * C_STAGE_F;
        const float* V = P + 128 * C_PST;

#pragma unroll
        for (int kk = 0; kk < 32; kk += 8) {
            uint32_t af[2][4], bf[4][2];
#pragma unroll
            for (int mt = 0; mt < 2; mt++) {
                int r0 = warpM * 32 + mt * 16 + g;
                af[mt][0] = tf32b(P[r0 * C_PST + kk + t]);
                af[mt][1] = tf32b(P[(r0 + 8) * C_PST + kk + t]);
                af[mt][2] = tf32b(P[r0 * C_PST + kk + t + 4]);
                af[mt][3] = tf32b(P[(r0 + 8) * C_PST + kk + t + 4]);
            }
#pragma unroll
            for (int nt = 0; nt < 4; nt++) {
                int n0 = warpN * 32 + nt * 8 + g;
                bf[nt][0] = tf32b(V[(kk + t) * C_VST + n0]);
                bf[nt][1] = tf32b(V[(kk + t + 4) * C_VST + n0]);
            }
#pragma unroll
            for (int mt = 0; mt < 2; mt++)
#pragma unroll
                for (int nt = 0; nt < 4; nt++)
                    mma_tf32(c[mt][nt], af[mt], bf[nt]);
        }
        __syncthreads();
    }

#pragma unroll
    for (int mt = 0; mt < 2; mt++) {
#pragma unroll
        for (int nt = 0; nt < 4; nt++) {
            int s0 = qt * 128 + warpM * 32 + mt * 16 + g;
            int d0 = warpN * 32 + nt * 8 + 2 * t;
#pragma unroll
            for (int half = 0; half < 2; half++) {
                int s = s0 + half * 8;
                size_t base = ((size_t)b * Sn + s) * Dn + h * DHn + d0;
                ctx[base] = c[mt][nt][half * 2 + 0];
                ctx[base + 1] = c[mt][nt][half * 2 + 1];
            }
        }
    }
}

// ---------------------------------------------------------------------------
// Launch
// ---------------------------------------------------------------------------
extern "C" void kernel_launch(void* const* d_in, const int* in_sizes, int n_in,
                              void* d_out, int out_size)
{
    const float* Q  = (const float*)d_in[0];
    const float* K  = (const float*)d_in[1];
    const float* V  = (const float*)d_in[2];
    const float* wq = (const float*)d_in[4];
    const float* bq = (const float*)d_in[5];
    const float* wk = (const float*)d_in[6];
    const float* bk = (const float*)d_in[7];
    const float* wv = (const float*)d_in[8];
    const float* bv = (const float*)d_in[9];
    const float* wo = (const float*)d_in[10];
    const float* bo = (const float*)d_in[11];

    float* out = (float*)d_out;

    float* attn;
    if ((size_t)out_size >= OUT_ELEMS + ATTN_ELEMS) {
        attn = out + OUT_ELEMS;
    } else {
        void* p = nullptr;
        cudaGetSymbolAddress(&p, g_attn_scratch);
        attn = (float*)p;
    }

    float *gq, *gk, *gv, *gctx;
    {
        void* p;
        cudaGetSymbolAddress(&p, g_q);   gq   = (float*)p;
        cudaGetSymbolAddress(&p, g_k);   gk   = (float*)p;
        cudaGetSymbolAddress(&p, g_v);   gv   = (float*)p;
        cudaGetSymbolAddress(&p, g_ctx); gctx = (float*)p;
    }

    cudaFuncSetAttribute(tf32_gemm_kernel,
                         cudaFuncAttributeMaxDynamicSharedMemorySize, GEMM_SMEM);
    cudaFuncSetAttribute(scores_kernel,
                         cudaFuncAttributeMaxDynamicSharedMemorySize, SCORES_SMEM);
    cudaFuncSetAttribute(ctx_kernel,
                         cudaFuncAttributeMaxDynamicSharedMemorySize, CTX_SMEM);

    dim3 gg(Dn / 128, Mn / 128);   // (8, 64)
    tf32_gemm_kernel<<<gg, 256, GEMM_SMEM>>>(Q, wq, bq, gq, 1);
    tf32_gemm_kernel<<<gg, 256, GEMM_SMEM>>>(K, wk, bk, gk, 1);
    tf32_gemm_kernel<<<gg, 256, GEMM_SMEM>>>(V, wv, bv, gv, 1);

    scores_kernel<<<dim3(NQT, BHn), 256, SCORES_SMEM>>>(gq, gk, attn);
    softmax_kernel<<<BHn * Sn, 256>>>(attn);
    ctx_kernel<<<dim3(NQT, BHn), 256, CTX_SMEM>>>(attn, gv, gctx);

    tf32_gemm_kernel<<<gg, 256, GEMM_SMEM>>>(gctx, wo, bo, out, 0);
}

// round 6
// speedup vs baseline: 3.2155x; 1.0683x over previous
#include <cuda_runtime.h>
#include <cstdint>
#include <math.h>

// Problem constants
#define Bn   4
#define Sn   2048
#define Dn   1024
#define Hn   16
#define DHn  64
#define BHn  (Bn * Hn)          // 64
#define Mn   (Bn * Sn)          // 8192
#define NQT  (Sn / 128)         // 16 q-tiles
#define SCALE_F 0.125f

#define OUT_ELEMS  ((size_t)Mn * Dn)            // 8,388,608
#define ATTN_ELEMS ((size_t)BHn * Sn * Sn)      // 268,435,456

// Scratch (device globals)
__device__ float g_q[Mn * Dn];            // [B,H,S,DH]
__device__ float g_k[Mn * Dn];
__device__ float g_v[Mn * Dn];
__device__ float g_ctx[Mn * Dn];          // [B,S,H*DH]
__device__ float g_attn_scratch[ATTN_ELEMS];

// ---------------------------------------------------------------------------
// PTX helpers
// ---------------------------------------------------------------------------
__device__ __forceinline__ uint32_t smem_u32(const void* p) {
    uint32_t a;
    asm("{ .reg .u64 t; cvta.to.shared.u64 t, %1; cvt.u32.u64 %0, t; }" : "=r"(a) : "l"(p));
    return a;
}
#define CP16(dst, src) \
    asm volatile("cp.async.cg.shared.global [%0], [%1], 16;" :: "r"(dst), "l"(src))
#define CP_COMMIT() asm volatile("cp.async.commit_group;")
#define CP_WAIT1()  asm volatile("cp.async.wait_group 1;")
#define CP_WAIT0()  asm volatile("cp.async.wait_group 0;")

__device__ __forceinline__ uint32_t tf32b(float f) {
    uint32_t r; asm("cvt.rna.tf32.f32 %0, %1;" : "=r"(r) : "f"(f));
    return r;
}
__device__ __forceinline__ void mma_tf32(float c[4], const uint32_t a[4], const uint32_t b[2]) {
    asm volatile(
        "mma.sync.aligned.m16n8k8.row.col.f32.tf32.tf32.f32 "
        "{%0,%1,%2,%3}, {%4,%5,%6,%7}, {%8,%9}, {%0,%1,%2,%3};"
        : "+f"(c[0]), "+f"(c[1]), "+f"(c[2]), "+f"(c[3])
        : "r"(a[0]), "r"(a[1]), "r"(a[2]), "r"(a[3]), "r"(b[0]), "r"(b[1]));
}

// ---------------------------------------------------------------------------
// tf32 mma GEMM (unchanged from R4): out = X[M,1024] @ W[1024,1024] + bias
// ---------------------------------------------------------------------------
#define G_AST 36
#define G_BST 132
#define G_STAGE_F (128 * G_AST + 32 * G_BST)
#define GEMM_SMEM (3 * G_STAGE_F * 4)

__global__ __launch_bounds__(256) void tf32_gemm_kernel(
    const float* __restrict__ X, const float* __restrict__ W,
    const float* __restrict__ bias, float* __restrict__ out, int mode)
{
    extern __shared__ float sm[];
    const int tid = threadIdx.x;
    const int wid = tid >> 5, lane = tid & 31;
    const int g = lane >> 2, t = lane & 3;
    const int warpM = wid & 1, warpN = wid >> 1;
    const int bm = blockIdx.y * 128, bn = blockIdx.x * 128;

    const uint32_t sbase = smem_u32(sm);

    float c[4][4][4];
#pragma unroll
    for (int i = 0; i < 4; i++)
#pragma unroll
        for (int j = 0; j < 4; j++)
#pragma unroll
            for (int k = 0; k < 4; k++) c[i][j][k] = 0.0f;

    auto issue = [&](int cidx, int buf) {
        const float* Xp = X + (size_t)bm * Dn + cidx * 32;
        const float* Wp = W + (size_t)(cidx * 32) * Dn + bn;
        uint32_t abase = sbase + buf * (G_STAGE_F * 4);
        uint32_t bbase = abase + 128 * G_AST * 4;
#pragma unroll
        for (int j = 0; j < 4; j++) {
            int ia = tid + j * 256;
            int ar = ia >> 3, ac = ia & 7;
            CP16(abase + ar * (G_AST * 4) + ac * 16, Xp + (size_t)ar * Dn + ac * 4);
            int br = ia >> 5, bc = ia & 31;
            CP16(bbase + br * (G_BST * 4) + bc * 16, Wp + (size_t)br * Dn + bc * 4);
        }
    };

    issue(0, 0); CP_COMMIT();
    issue(1, 1); CP_COMMIT();

    const int NCH = Dn / 32;
    for (int s = 0; s < NCH; s++) {
        int buf = s % 3;
        if (s < NCH - 2) CP_WAIT1(); else CP_WAIT0();
        __syncthreads();
        if (s + 2 < NCH) { issue(s + 2, (s + 2) % 3); CP_COMMIT(); }

        const float* A = sm + buf * G_STAGE_F;
        const float* B = A + 128 * G_AST;
#pragma unroll
        for (int kk = 0; kk < 32; kk += 8) {
            uint32_t af[4][4], bf[4][2];
#pragma unroll
            for (int mt = 0; mt < 4; mt++) {
                int r0 = warpM * 64 + mt * 16 + g;
                af[mt][0] = tf32b(A[r0 * G_AST + kk + t]);
                af[mt][1] = tf32b(A[(r0 + 8) * G_AST + kk + t]);
                af[mt][2] = tf32b(A[r0 * G_AST + kk + t + 4]);
                af[mt][3] = tf32b(A[(r0 + 8) * G_AST + kk + t + 4]);
            }
#pragma unroll
            for (int nt = 0; nt < 4; nt++) {
                int n0 = warpN * 32 + nt * 8 + g;
                bf[nt][0] = tf32b(B[(kk + t) * G_BST + n0]);
                bf[nt][1] = tf32b(B[(kk + t + 4) * G_BST + n0]);
            }
#pragma unroll
            for (int mt = 0; mt < 4; mt++)
#pragma unroll
                for (int nt = 0; nt < 4; nt++)
                    mma_tf32(c[mt][nt], af[mt], bf[nt]);
        }
    }

#pragma unroll
    for (int mt = 0; mt < 4; mt++) {
#pragma unroll
        for (int nt = 0; nt < 4; nt++) {
            int m0 = bm + warpM * 64 + mt * 16 + g;
            int n0 = bn + warpN * 32 + nt * 8 + 2 * t;
#pragma unroll
            for (int half = 0; half < 2; half++) {
                int m = m0 + half * 8;
                float v0 = c[mt][nt][half * 2 + 0] + bias[n0];
                float v1 = c[mt][nt][half * 2 + 1] + bias[n0 + 1];
                if (mode == 0) {
                    out[(size_t)m * Dn + n0] = v0;
                    out[(size_t)m * Dn + n0 + 1] = v1;
                } else {
                    int b = m >> 11, sq = m & (Sn - 1);
                    int h = n0 >> 6, d = n0 & 63;
                    size_t base = (((size_t)b * Hn + h) * Sn + sq) * DHn + d;
                    out[base] = v0;
                    out[base + 1] = v1;
                }
            }
        }
    }
}

// ---------------------------------------------------------------------------
// Fused attention: scores + softmax(no-max, exact) + attn-write + P@V.
// grid (NQT, BHn); CTA = one q-tile of 128 rows.
// K/V tiles of 64 rows, double-buffered cp.async.
// Phase 1: row sums of exp(S).  Phase 2: P = exp(S)*inv_l -> attn + smem, O += P@V.
// ---------------------------------------------------------------------------
#define F_ST   68
#define F_Q    0                          // 128 x 68
#define F_K0   (128 * F_ST)               // 64 x 68
#define F_K1   (F_K0 + 64 * F_ST)
#define F_V0   (F_K1 + 64 * F_ST)
#define F_V1   (F_V0 + 64 * F_ST)
#define F_P    (F_V1 + 64 * F_ST)         // 128 x 68
#define F_L    (F_P + 128 * F_ST)         // 128
#define F_INV  (F_L + 128)                // 128
#define FUSED_SMEM ((F_INV + 128) * 4)    // 140,288 bytes

__global__ __launch_bounds__(256) void fused_attn_kernel(
    const float* __restrict__ q, const float* __restrict__ k,
    const float* __restrict__ v, float* __restrict__ attn,
    float* __restrict__ ctx)
{
    extern __shared__ float sm[];
    const int bh = blockIdx.y;
    const int qt = (NQT - 1) - blockIdx.x;   // heavy tiles first
    const int b = bh >> 4, h = bh & 15;

    const int tid = threadIdx.x;
    const int wid = tid >> 5, lane = tid & 31;
    const int g = lane >> 2, t = lane & 3;
    const int warpM = wid & 1, warpN = wid >> 1;   // 2 x 4

    const uint32_t sbase = smem_u32(sm);
    const float* qb = q + ((size_t)bh * Sn + qt * 128) * DHn;
    const float* kbase = k + (size_t)bh * Sn * DHn;
    const float* vbase = v + (size_t)bh * Sn * DHn;
    float* attn_base = attn + ((size_t)bh * Sn + qt * 128) * Sn;

    const int ntiles = 2 * (qt + 1);   // 64-row K/V tiles

    auto issueK = [&](int c, int buf) {
        const float* kb = kbase + (size_t)(c * 64) * DHn;
        uint32_t dst = sbase + (F_K0 + buf * 64 * F_ST) * 4;
#pragma unroll
        for (int j = 0; j < 4; j++) {
            int ia = tid + j * 256;
            int r = ia >> 4, c4 = ia & 15;
            CP16(dst + r * (F_ST * 4) + c4 * 16, kb + (size_t)r * DHn + c4 * 4);
        }
    };
    auto issueV = [&](int c, int buf) {
        const float* vb = vbase + (size_t)(c * 64) * DHn;
        uint32_t dst = sbase + (F_V0 + buf * 64 * F_ST) * 4;
#pragma unroll
        for (int j = 0; j < 4; j++) {
            int ia = tid + j * 256;
            int r = ia >> 4, c4 = ia & 15;
            CP16(dst + r * (F_ST * 4) + c4 * 16, vb + (size_t)r * DHn + c4 * 4);
        }
    };

    // Q load (cp.async) + first K tile
    {
        uint32_t qdst = sbase + F_Q * 4;
#pragma unroll
        for (int j = 0; j < 8; j++) {
            int ia = tid + j * 256;
            int r = ia >> 4, c4 = ia & 15;
            CP16(qdst + r * (F_ST * 4) + c4 * 16, qb + (size_t)r * DHn + c4 * 4);
        }
        issueK(0, 0);
        CP_COMMIT();
    }

    // zero-fill causal upper region (overlaps with async loads)
    {
        int zc0 = (qt + 1) * 128;
        int nz4 = (Sn - zc0) >> 2;
        if (nz4 > 0) {
            const float4 z = make_float4(0.f, 0.f, 0.f, 0.f);
            for (int idx = tid; idx < 128 * nz4; idx += 256) {
                int r = idx / nz4, cc = idx - r * nz4;
                *(float4*)(attn_base + (size_t)r * Sn + zc0 + cc * 4) = z;
            }
        }
    }

    if (tid < 128) sm[F_L + tid] = 0.0f;

    const float* Qs = sm + F_Q;

    // ---------------- Phase 1: row sums ----------------
    float rs[8];
#pragma unroll
    for (int i = 0; i < 8; i++) rs[i] = 0.0f;

    for (int c = 0; c < ntiles; c++) {
        CP_WAIT0();
        __syncthreads();
        if (c + 1 < ntiles) { issueK(c + 1, (c + 1) & 1); CP_COMMIT(); }

        const float* K = sm + F_K0 + (c & 1) * 64 * F_ST;
        float cs[4][2][4];
#pragma unroll
        for (int i = 0; i < 4; i++)
#pragma unroll
            for (int j = 0; j < 2; j++)
#pragma unroll
                for (int kk = 0; kk < 4; kk++) cs[i][j][kk] = 0.0f;

#pragma unroll
        for (int kk = 0; kk < 64; kk += 8) {
            uint32_t af[4][4], bf[2][2];
#pragma unroll
            for (int mt = 0; mt < 4; mt++) {
                int r0 = warpM * 64 + mt * 16 + g;
                af[mt][0] = tf32b(Qs[r0 * F_ST + kk + t]);
                af[mt][1] = tf32b(Qs[(r0 + 8) * F_ST + kk + t]);
                af[mt][2] = tf32b(Qs[r0 * F_ST + kk + t + 4]);
                af[mt][3] = tf32b(Qs[(r0 + 8) * F_ST + kk + t + 4]);
            }
#pragma unroll
            for (int nt = 0; nt < 2; nt++) {
                int n0 = warpN * 16 + nt * 8 + g;
                bf[nt][0] = tf32b(K[n0 * F_ST + kk + t]);
                bf[nt][1] = tf32b(K[n0 * F_ST + kk + t + 4]);
            }
#pragma unroll
            for (int mt = 0; mt < 4; mt++)
#pragma unroll
                for (int nt = 0; nt < 2; nt++)
                    mma_tf32(cs[mt][nt], af[mt], bf[nt]);
        }

        // exp + causal mask + accumulate row sums
#pragma unroll
        for (int mt = 0; mt < 4; mt++) {
#pragma unroll
            for (int half = 0; half < 2; half++) {
                int qi = qt * 128 + warpM * 64 + mt * 16 + g + half * 8;
                float acc = 0.0f;
#pragma unroll
                for (int nt = 0; nt < 2; nt++) {
                    int kj = c * 64 + warpN * 16 + nt * 8 + 2 * t;
                    float e0 = (kj <= qi) ? __expf(cs[mt][nt][half * 2] * SCALE_F) : 0.0f;
                    float e1 = (kj + 1 <= qi) ? __expf(cs[mt][nt][half * 2 + 1] * SCALE_F) : 0.0f;
                    acc += e0 + e1;
                }
                rs[mt * 2 + half] += acc;
            }
        }
    }

    // reduce over quad (t) then atomically into smem ls
#pragma unroll
    for (int i = 0; i < 8; i++) {
        rs[i] += __shfl_xor_sync(0xffffffffu, rs[i], 1);
        rs[i] += __shfl_xor_sync(0xffffffffu, rs[i], 2);
    }
    if (t == 0) {
#pragma unroll
        for (int i = 0; i < 8; i++) {
            int row = warpM * 64 + (i >> 1) * 16 + g + (i & 1) * 8;
            atomicAdd(&sm[F_L + row], rs[i]);
        }
    }
    __syncthreads();
    if (tid < 128) sm[F_INV + tid] = 1.0f / sm[F_L + tid];

    // ---------------- Phase 2: P write + P@V ----------------
    float o[4][2][4];
#pragma unroll
    for (int i = 0; i < 4; i++)
#pragma unroll
        for (int j = 0; j < 2; j++)
#pragma unroll
            for (int kk = 0; kk < 4; kk++) o[i][j][kk] = 0.0f;

    issueK(0, 0); issueV(0, 0); CP_COMMIT();

    float* Ps = sm + F_P;
    const float* invl = sm + F_INV;

    for (int c = 0; c < ntiles; c++) {
        CP_WAIT0();
        __syncthreads();
        if (c + 1 < ntiles) {
            issueK(c + 1, (c + 1) & 1);
            issueV(c + 1, (c + 1) & 1);
            CP_COMMIT();
        }

        const float* K = sm + F_K0 + (c & 1) * 64 * F_ST;
        const float* V = sm + F_V0 + (c & 1) * 64 * F_ST;

        float cs[4][2][4];
#pragma unroll
        for (int i = 0; i < 4; i++)
#pragma unroll
            for (int j = 0; j < 2; j++)
#pragma unroll
                for (int kk = 0; kk < 4; kk++) cs[i][j][kk] = 0.0f;

#pragma unroll
        for (int kk = 0; kk < 64; kk += 8) {
            uint32_t af[4][4], bf[2][2];
#pragma unroll
            for (int mt = 0; mt < 4; mt++) {
                int r0 = warpM * 64 + mt * 16 + g;
                af[mt][0] = tf32b(Qs[r0 * F_ST + kk + t]);
                af[mt][1] = tf32b(Qs[(r0 + 8) * F_ST + kk + t]);
                af[mt][2] = tf32b(Qs[r0 * F_ST + kk + t + 4]);
                af[mt][3] = tf32b(Qs[(r0 + 8) * F_ST + kk + t + 4]);
            }
#pragma unroll
            for (int nt = 0; nt < 2; nt++) {
                int n0 = warpN * 16 + nt * 8 + g;
                bf[nt][0] = tf32b(K[n0 * F_ST + kk + t]);
                bf[nt][1] = tf32b(K[n0 * F_ST + kk + t + 4]);
            }
#pragma unroll
            for (int mt = 0; mt < 4; mt++)
#pragma unroll
                for (int nt = 0; nt < 2; nt++)
                    mma_tf32(cs[mt][nt], af[mt], bf[nt]);
        }

        // P = exp(S)*inv_l -> gmem attn + smem Ps
#pragma unroll
        for (int mt = 0; mt < 4; mt++) {
#pragma unroll
            for (int half = 0; half < 2; half++) {
                int rloc = warpM * 64 + mt * 16 + g + half * 8;
                int qi = qt * 128 + rloc;
                float inv = invl[rloc];
#pragma unroll
                for (int nt = 0; nt < 2; nt++) {
                    int klc = warpN * 16 + nt * 8 + 2 * t;
                    int kj = c * 64 + klc;
                    float p0 = (kj <= qi) ? __expf(cs[mt][nt][half * 2] * SCALE_F) * inv : 0.0f;
                    float p1 = (kj + 1 <= qi) ? __expf(cs[mt][nt][half * 2 + 1] * SCALE_F) * inv : 0.0f;
                    *(float2*)(attn_base + (size_t)rloc * Sn + kj) = make_float2(p0, p1);
                    Ps[rloc * F_ST + klc] = p0;
                    Ps[rloc * F_ST + klc + 1] = p1;
                }
            }
        }
        __syncthreads();

        // O += P @ V   (P: 128x64, V: 64x64)
#pragma unroll
        for (int kk = 0; kk < 64; kk += 8) {
            uint32_t af[4][4], bf[2][2];
#pragma unroll
            for (int mt = 0; mt < 4; mt++) {
                int r0 = warpM * 64 + mt * 16 + g;
                af[mt][0] = tf32b(Ps[r0 * F_ST + kk + t]);
                af[mt][1] = tf32b(Ps[(r0 + 8) * F_ST + kk + t]);
                af[mt][2] = tf32b(Ps[r0 * F_ST + kk + t + 4]);
                af[mt][3] = tf32b(Ps[(r0 + 8) * F_ST + kk + t + 4]);
            }
#pragma unroll
            for (int nt = 0; nt < 2; nt++) {
                int n0 = warpN * 16 + nt * 8 + g;
                bf[nt][0] = tf32b(V[(kk + t) * F_ST + n0]);
                bf[nt][1] = tf32b(V[(kk + t + 4) * F_ST + n0]);
            }
#pragma unroll
            for (int mt = 0; mt < 4; mt++)
#pragma unroll
                for (int nt = 0; nt < 2; nt++)
                    mma_tf32(o[mt][nt], af[mt], bf[nt]);
        }
    }

    // write O to ctx [B,S,H*DH]
#pragma unroll
    for (int mt = 0; mt < 4; mt++) {
#pragma unroll
        for (int nt = 0; nt < 2; nt++) {
            int s0 = qt * 128 + warpM * 64 + mt * 16 + g;
            int d0 = warpN * 16 + nt * 8 + 2 * t;
#pragma unroll
            for (int half = 0; half < 2; half++) {
                int s = s0 + half * 8;
                size_t base = ((size_t)b * Sn + s) * Dn + h * DHn + d0;
                ctx[base] = o[mt][nt][half * 2 + 0];
                ctx[base + 1] = o[mt][nt][half * 2 + 1];
            }
        }
    }
}

// ---------------------------------------------------------------------------
// Launch
// ---------------------------------------------------------------------------
extern "C" void kernel_launch(void* const* d_in, const int* in_sizes, int n_in,
                              void* d_out, int out_size)
{
    const float* Q  = (const float*)d_in[0];
    const float* K  = (const float*)d_in[1];
    const float* V  = (const float*)d_in[2];
    const float* wq = (const float*)d_in[4];
    const float* bq = (const float*)d_in[5];
    const float* wk = (const float*)d_in[6];
    const float* bk = (const float*)d_in[7];
    const float* wv = (const float*)d_in[8];
    const float* bv = (const float*)d_in[9];
    const float* wo = (const float*)d_in[10];
    const float* bo = (const float*)d_in[11];

    float* out = (float*)d_out;

    float* attn;
    if ((size_t)out_size >= OUT_ELEMS + ATTN_ELEMS) {
        attn = out + OUT_ELEMS;
    } else {
        void* p = nullptr;
        cudaGetSymbolAddress(&p, g_attn_scratch);
        attn = (float*)p;
    }

    float *gq, *gk, *gv, *gctx;
    {
        void* p;
        cudaGetSymbolAddress(&p, g_q);   gq   = (float*)p;
        cudaGetSymbolAddress(&p, g_k);   gk   = (float*)p;
        cudaGetSymbolAddress(&p, g_v);   gv   = (float*)p;
        cudaGetSymbolAddress(&p, g_ctx); gctx = (float*)p;
    }

    cudaFuncSetAttribute(tf32_gemm_kernel,
                         cudaFuncAttributeMaxDynamicSharedMemorySize, GEMM_SMEM);
    cudaFuncSetAttribute(fused_attn_kernel,
                         cudaFuncAttributeMaxDynamicSharedMemorySize, FUSED_SMEM);

    dim3 gg(Dn / 128, Mn / 128);   // (8, 64)
    tf32_gemm_kernel<<<gg, 256, GEMM_SMEM>>>(Q, wq, bq, gq, 1);
    tf32_gemm_kernel<<<gg, 256, GEMM_SMEM>>>(K, wk, bk, gk, 1);
    tf32_gemm_kernel<<<gg, 256, GEMM_SMEM>>>(V, wv, bv, gv, 1);

    fused_attn_kernel<<<dim3(NQT, BHn), 256, FUSED_SMEM>>>(gq, gk, gv, attn, gctx);

    tf32_gemm_kernel<<<gg, 256, GEMM_SMEM>>>(gctx, wo, bo, out, 0);
}

// round 7
// speedup vs baseline: 3.5347x; 1.0993x over previous
#include <cuda_runtime.h>
#include <cstdint>
#include <math.h>

// Problem constants
#define Bn   4
#define Sn   2048
#define Dn   1024
#define Hn   16
#define DHn  64
#define BHn  (Bn * Hn)          // 64
#define Mn   (Bn * Sn)          // 8192
#define NQT  (Sn / 128)         // 16 q-tiles
#define SCALE_F 0.125f

#define OUT_ELEMS  ((size_t)Mn * Dn)            // 8,388,608
#define ATTN_ELEMS ((size_t)BHn * Sn * Sn)      // 268,435,456

// Scratch (device globals)
__device__ float g_q[Mn * Dn];            // [B,H,S,DH]
__device__ float g_k[Mn * Dn];
__device__ float g_v[Mn * Dn];
__device__ float g_ctx[Mn * Dn];          // [B,S,H*DH]
__device__ float g_attn_scratch[ATTN_ELEMS];

// ---------------------------------------------------------------------------
// PTX helpers
// ---------------------------------------------------------------------------
__device__ __forceinline__ uint32_t smem_u32(const void* p) {
    uint32_t a;
    asm("{ .reg .u64 t; cvta.to.shared.u64 t, %1; cvt.u32.u64 %0, t; }" : "=r"(a) : "l"(p));
    return a;
}
#define CP16(dst, src) \
    asm volatile("cp.async.cg.shared.global [%0], [%1], 16;" :: "r"(dst), "l"(src))
#define CP_COMMIT() asm volatile("cp.async.commit_group;")
#define CP_WAIT1()  asm volatile("cp.async.wait_group 1;")
#define CP_WAIT0()  asm volatile("cp.async.wait_group 0;")

__device__ __forceinline__ uint32_t tf32b(float f) {
    uint32_t r; asm("cvt.rna.tf32.f32 %0, %1;" : "=r"(r) : "f"(f));
    return r;
}
__device__ __forceinline__ void mma_tf32(float c[4], const uint32_t a[4], const uint32_t b[2]) {
    asm volatile(
        "mma.sync.aligned.m16n8k8.row.col.f32.tf32.tf32.f32 "
        "{%0,%1,%2,%3}, {%4,%5,%6,%7}, {%8,%9}, {%0,%1,%2,%3};"
        : "+f"(c[0]), "+f"(c[1]), "+f"(c[2]), "+f"(c[3])
        : "r"(a[0]), "r"(a[1]), "r"(a[2]), "r"(a[3]), "r"(b[0]), "r"(b[1]));
}

// ---------------------------------------------------------------------------
// tf32 mma GEMM, 2-stage pipeline, 2 CTAs/SM. QKV fused via blockIdx.z.
// ---------------------------------------------------------------------------
#define G_AST 36
#define G_BST 132
#define G_STAGE_F (128 * G_AST + 32 * G_BST)
#define GEMM_SMEM (2 * G_STAGE_F * 4)        // 70,656 bytes

__global__ __launch_bounds__(256, 2) void tf32_gemm_kernel(
    const float* __restrict__ X0, const float* __restrict__ X1, const float* __restrict__ X2,
    const float* __restrict__ W0, const float* __restrict__ W1, const float* __restrict__ W2,
    const float* __restrict__ B0, const float* __restrict__ B1, const float* __restrict__ B2,
    float* __restrict__ O0, float* __restrict__ O1, float* __restrict__ O2,
    int mode)
{
    extern __shared__ float sm[];
    const int z = blockIdx.z;
    const float* X    = (z == 0) ? X0 : (z == 1) ? X1 : X2;
    const float* W    = (z == 0) ? W0 : (z == 1) ? W1 : W2;
    const float* bias = (z == 0) ? B0 : (z == 1) ? B1 : B2;
    float* out        = (z == 0) ? O0 : (z == 1) ? O1 : O2;

    const int tid = threadIdx.x;
    const int wid = tid >> 5, lane = tid & 31;
    const int g = lane >> 2, t = lane & 3;
    const int warpM = wid & 1, warpN = wid >> 1;
    const int bm = blockIdx.y * 128, bn = blockIdx.x * 128;

    const uint32_t sbase = smem_u32(sm);

    float c[4][4][4];
#pragma unroll
    for (int i = 0; i < 4; i++)
#pragma unroll
        for (int j = 0; j < 4; j++)
#pragma unroll
            for (int k = 0; k < 4; k++) c[i][j][k] = 0.0f;

    auto issue = [&](int cidx, int buf) {
        const float* Xp = X + (size_t)bm * Dn + cidx * 32;
        const float* Wp = W + (size_t)(cidx * 32) * Dn + bn;
        uint32_t abase = sbase + buf * (G_STAGE_F * 4);
        uint32_t bbase = abase + 128 * G_AST * 4;
#pragma unroll
        for (int j = 0; j < 4; j++) {
            int ia = tid + j * 256;
            int ar = ia >> 3, ac = ia & 7;
            CP16(abase + ar * (G_AST * 4) + ac * 16, Xp + (size_t)ar * Dn + ac * 4);
            int br = ia >> 5, bc = ia & 31;
            CP16(bbase + br * (G_BST * 4) + bc * 16, Wp + (size_t)br * Dn + bc * 4);
        }
    };

    issue(0, 0); CP_COMMIT();

    const int NCH = Dn / 32;   // 32
    for (int s = 0; s < NCH; s++) {
        CP_WAIT0();
        __syncthreads();
        if (s + 1 < NCH) { issue(s + 1, (s + 1) & 1); CP_COMMIT(); }

        const float* A = sm + (s & 1) * G_STAGE_F;
        const float* B = A + 128 * G_AST;
#pragma unroll
        for (int kk = 0; kk < 32; kk += 8) {
            uint32_t af[4][4], bf[4][2];
#pragma unroll
            for (int mt = 0; mt < 4; mt++) {
                int r0 = warpM * 64 + mt * 16 + g;
                af[mt][0] = tf32b(A[r0 * G_AST + kk + t]);
                af[mt][1] = tf32b(A[(r0 + 8) * G_AST + kk + t]);
                af[mt][2] = tf32b(A[r0 * G_AST + kk + t + 4]);
                af[mt][3] = tf32b(A[(r0 + 8) * G_AST + kk + t + 4]);
            }
#pragma unroll
            for (int nt = 0; nt < 4; nt++) {
                int n0 = warpN * 32 + nt * 8 + g;
                bf[nt][0] = tf32b(B[(kk + t) * G_BST + n0]);
                bf[nt][1] = tf32b(B[(kk + t + 4) * G_BST + n0]);
            }
#pragma unroll
            for (int mt = 0; mt < 4; mt++)
#pragma unroll
                for (int nt = 0; nt < 4; nt++)
                    mma_tf32(c[mt][nt], af[mt], bf[nt]);
        }
    }

#pragma unroll
    for (int mt = 0; mt < 4; mt++) {
#pragma unroll
        for (int nt = 0; nt < 4; nt++) {
            int m0 = bm + warpM * 64 + mt * 16 + g;
            int n0 = bn + warpN * 32 + nt * 8 + 2 * t;
#pragma unroll
            for (int half = 0; half < 2; half++) {
                int m = m0 + half * 8;
                float v0 = c[mt][nt][half * 2 + 0] + bias[n0];
                float v1 = c[mt][nt][half * 2 + 1] + bias[n0 + 1];
                if (mode == 0) {
                    out[(size_t)m * Dn + n0] = v0;
                    out[(size_t)m * Dn + n0 + 1] = v1;
                } else {
                    int b = m >> 11, sq = m & (Sn - 1);
                    int h = n0 >> 6, d = n0 & 63;
                    size_t base = (((size_t)b * Hn + h) * Sn + sq) * DHn + d;
                    out[base] = v0;
                    out[base + 1] = v1;
                }
            }
        }
    }
}

// ---------------------------------------------------------------------------
// Fused attention, 2 CTAs/SM (105.5 KB smem).
// Phase 1: row sums of exp(QK^T), K ping-pong in bufs A/B.
// Phase 2: K in A, V in B; V-load overlaps S-mma, K(c+1)-load overlaps exp.
// ---------------------------------------------------------------------------
#define F_ST   68
#define F_Q    0                          // 128 x 68
#define F_A    (128 * F_ST)               // 64 x 68
#define F_B    (F_A + 64 * F_ST)          // 64 x 68
#define F_P    (F_B + 64 * F_ST)          // 128 x 68
#define F_L    (F_P + 128 * F_ST)         // 128
#define F_INV  (F_L + 128)                // 128
#define FUSED_SMEM ((F_INV + 128) * 4)    // 105,472 bytes

__global__ __launch_bounds__(256, 2) void fused_attn_kernel(
    const float* __restrict__ q, const float* __restrict__ k,
    const float* __restrict__ v, float* __restrict__ attn,
    float* __restrict__ ctx)
{
    extern __shared__ float sm[];
    const int bh = blockIdx.y;
    const int qt = (NQT - 1) - blockIdx.x;   // heavy tiles first
    const int b = bh >> 4, h = bh & 15;

    const int tid = threadIdx.x;
    const int wid = tid >> 5, lane = tid & 31;
    const int g = lane >> 2, t = lane & 3;
    const int warpM = wid & 1, warpN = wid >> 1;   // 2 x 4

    const uint32_t sbase = smem_u32(sm);
    const float* qb = q + ((size_t)bh * Sn + qt * 128) * DHn;
    const float* kbase = k + (size_t)bh * Sn * DHn;
    const float* vbase = v + (size_t)bh * Sn * DHn;
    float* attn_base = attn + ((size_t)bh * Sn + qt * 128) * Sn;

    const int ntiles = 2 * (qt + 1);   // 64-row K/V tiles

    auto issueK = [&](int c, uint32_t bufoff) {
        const float* kb = kbase + (size_t)(c * 64) * DHn;
        uint32_t dst = sbase + bufoff * 4;
#pragma unroll
        for (int j = 0; j < 4; j++) {
            int ia = tid + j * 256;
            int r = ia >> 4, c4 = ia & 15;
            CP16(dst + r * (F_ST * 4) + c4 * 16, kb + (size_t)r * DHn + c4 * 4);
        }
    };
    auto issueV = [&](int c, uint32_t bufoff) {
        const float* vb = vbase + (size_t)(c * 64) * DHn;
        uint32_t dst = sbase + bufoff * 4;
#pragma unroll
        for (int j = 0; j < 4; j++) {
            int ia = tid + j * 256;
            int r = ia >> 4, c4 = ia & 15;
            CP16(dst + r * (F_ST * 4) + c4 * 16, vb + (size_t)r * DHn + c4 * 4);
        }
    };

    // Q load + first K tile
    {
        uint32_t qdst = sbase + F_Q * 4;
#pragma unroll
        for (int j = 0; j < 8; j++) {
            int ia = tid + j * 256;
            int r = ia >> 4, c4 = ia & 15;
            CP16(qdst + r * (F_ST * 4) + c4 * 16, qb + (size_t)r * DHn + c4 * 4);
        }
        issueK(0, F_A);
        CP_COMMIT();
    }

    // zero-fill causal upper region (overlaps async loads)
    {
        int zc0 = (qt + 1) * 128;
        int nz4 = (Sn - zc0) >> 2;
        if (nz4 > 0) {
            const float4 z = make_float4(0.f, 0.f, 0.f, 0.f);
            for (int idx = tid; idx < 128 * nz4; idx += 256) {
                int r = idx / nz4, cc = idx - r * nz4;
                *(float4*)(attn_base + (size_t)r * Sn + zc0 + cc * 4) = z;
            }
        }
    }

    if (tid < 128) sm[F_L + tid] = 0.0f;

    const float* Qs = sm + F_Q;

    // ---------------- Phase 1: row sums of exp(S) ----------------
    float rs[8];
#pragma unroll
    for (int i = 0; i < 8; i++) rs[i] = 0.0f;

    for (int c = 0; c < ntiles; c++) {
        CP_WAIT0();
        __syncthreads();
        if (c + 1 < ntiles) {
            issueK(c + 1, ((c + 1) & 1) ? F_B : F_A);
            CP_COMMIT();
        }

        const float* K = sm + ((c & 1) ? F_B : F_A);
        float cs[4][2][4];
#pragma unroll
        for (int i = 0; i < 4; i++)
#pragma unroll
            for (int j = 0; j < 2; j++)
#pragma unroll
                for (int kk = 0; kk < 4; kk++) cs[i][j][kk] = 0.0f;

#pragma unroll
        for (int kk = 0; kk < 64; kk += 8) {
            uint32_t af[4][4], bf[2][2];
#pragma unroll
            for (int mt = 0; mt < 4; mt++) {
                int r0 = warpM * 64 + mt * 16 + g;
                af[mt][0] = tf32b(Qs[r0 * F_ST + kk + t]);
                af[mt][1] = tf32b(Qs[(r0 + 8) * F_ST + kk + t]);
                af[mt][2] = tf32b(Qs[r0 * F_ST + kk + t + 4]);
                af[mt][3] = tf32b(Qs[(r0 + 8) * F_ST + kk + t + 4]);
            }
#pragma unroll
            for (int nt = 0; nt < 2; nt++) {
                int n0 = warpN * 16 + nt * 8 + g;
                bf[nt][0] = tf32b(K[n0 * F_ST + kk + t]);
                bf[nt][1] = tf32b(K[n0 * F_ST + kk + t + 4]);
            }
#pragma unroll
            for (int mt = 0; mt < 4; mt++)
#pragma unroll
                for (int nt = 0; nt < 2; nt++)
                    mma_tf32(cs[mt][nt], af[mt], bf[nt]);
        }

#pragma unroll
        for (int mt = 0; mt < 4; mt++) {
#pragma unroll
            for (int half = 0; half < 2; half++) {
                int qi = qt * 128 + warpM * 64 + mt * 16 + g + half * 8;
                float acc = 0.0f;
#pragma unroll
                for (int nt = 0; nt < 2; nt++) {
                    int kj = c * 64 + warpN * 16 + nt * 8 + 2 * t;
                    float e0 = (kj <= qi) ? __expf(cs[mt][nt][half * 2] * SCALE_F) : 0.0f;
                    float e1 = (kj + 1 <= qi) ? __expf(cs[mt][nt][half * 2 + 1] * SCALE_F) : 0.0f;
                    acc += e0 + e1;
                }
                rs[mt * 2 + half] += acc;
            }
        }
    }

    // all warps done with bufs; prefetch phase-2 tiles, then reduce row sums
    __syncthreads();
    issueK(0, F_A); CP_COMMIT();
    issueV(0, F_B); CP_COMMIT();

#pragma unroll
    for (int i = 0; i < 8; i++) {
        rs[i] += __shfl_xor_sync(0xffffffffu, rs[i], 1);
        rs[i] += __shfl_xor_sync(0xffffffffu, rs[i], 2);
    }
    if (t == 0) {
#pragma unroll
        for (int i = 0; i < 8; i++) {
            int row = warpM * 64 + (i >> 1) * 16 + g + (i & 1) * 8;
            atomicAdd(&sm[F_L + row], rs[i]);
        }
    }
    __syncthreads();
    if (tid < 128) sm[F_INV + tid] = 1.0f / sm[F_L + tid];
    __syncthreads();

    // ---------------- Phase 2: P write + P@V ----------------
    float o[4][2][4];
#pragma unroll
    for (int i = 0; i < 4; i++)
#pragma unroll
        for (int j = 0; j < 2; j++)
#pragma unroll
            for (int kk = 0; kk < 4; kk++) o[i][j][kk] = 0.0f;

    float* Ps = sm + F_P;
    const float* invl = sm + F_INV;
    const float* Kb = sm + F_A;
    const float* Vb = sm + F_B;

    for (int c = 0; c < ntiles; c++) {
        // K(c) ready (V(c) is the newest pending group)
        CP_WAIT1();
        __syncthreads();

        float cs[4][2][4];
#pragma unroll
        for (int i = 0; i < 4; i++)
#pragma unroll
            for (int j = 0; j < 2; j++)
#pragma unroll
                for (int kk = 0; kk < 4; kk++) cs[i][j][kk] = 0.0f;

#pragma unroll
        for (int kk = 0; kk < 64; kk += 8) {
            uint32_t af[4][4], bf[2][2];
#pragma unroll
            for (int mt = 0; mt < 4; mt++) {
                int r0 = warpM * 64 + mt * 16 + g;
                af[mt][0] = tf32b(Qs[r0 * F_ST + kk + t]);
                af[mt][1] = tf32b(Qs[(r0 + 8) * F_ST + kk + t]);
                af[mt][2] = tf32b(Qs[r0 * F_ST + kk + t + 4]);
                af[mt][3] = tf32b(Qs[(r0 + 8) * F_ST + kk + t + 4]);
            }
#pragma unroll
            for (int nt = 0; nt < 2; nt++) {
                int n0 = warpN * 16 + nt * 8 + g;
                bf[nt][0] = tf32b(Kb[n0 * F_ST + kk + t]);
                bf[nt][1] = tf32b(Kb[n0 * F_ST + kk + t + 4]);
            }
#pragma unroll
            for (int mt = 0; mt < 4; mt++)
#pragma unroll
                for (int nt = 0; nt < 2; nt++)
                    mma_tf32(cs[mt][nt], af[mt], bf[nt]);
        }

        // all warps done reading K buf -> prefetch K(c+1) into A
        __syncthreads();
        if (c + 1 < ntiles) { issueK(c + 1, F_A); CP_COMMIT(); }

        // P = exp(S)*inv_l -> gmem attn + smem Ps  (overlaps K(c+1) load)
#pragma unroll
        for (int mt = 0; mt < 4; mt++) {
#pragma unroll
            for (int half = 0; half < 2; half++) {
                int rloc = warpM * 64 + mt * 16 + g + half * 8;
                int qi = qt * 128 + rloc;
                float inv = invl[rloc];
#pragma unroll
                for (int nt = 0; nt < 2; nt++) {
                    int klc = warpN * 16 + nt * 8 + 2 * t;
                    int kj = c * 64 + klc;
                    float p0 = (kj <= qi) ? __expf(cs[mt][nt][half * 2] * SCALE_F) * inv : 0.0f;
                    float p1 = (kj + 1 <= qi) ? __expf(cs[mt][nt][half * 2 + 1] * SCALE_F) * inv : 0.0f;
                    *(float2*)(attn_base + (size_t)rloc * Sn + kj) = make_float2(p0, p1);
                    Ps[rloc * F_ST + klc] = p0;
                    Ps[rloc * F_ST + klc + 1] = p1;
                }
            }
        }

        // V(c) ready
        if (c + 1 < ntiles) CP_WAIT1(); else CP_WAIT0();
        __syncthreads();   // Ps visible + V ready

        // O += P @ V
#pragma unroll
        for (int kk = 0; kk < 64; kk += 8) {
            uint32_t af[4][4], bf[2][2];
#pragma unroll
            for (int mt = 0; mt < 4; mt++) {
                int r0 = warpM * 64 + mt * 16 + g;
                af[mt][0] = tf32b(Ps[r0 * F_ST + kk + t]);
                af[mt][1] = tf32b(Ps[(r0 + 8) * F_ST + kk + t]);
                af[mt][2] = tf32b(Ps[r0 * F_ST + kk + t + 4]);
                af[mt][3] = tf32b(Ps[(r0 + 8) * F_ST + kk + t + 4]);
            }
#pragma unroll
            for (int nt = 0; nt < 2; nt++) {
                int n0 = warpN * 16 + nt * 8 + g;
                bf[nt][0] = tf32b(Vb[(kk + t) * F_ST + n0]);
                bf[nt][1] = tf32b(Vb[(kk + t + 4) * F_ST + n0]);
            }
#pragma unroll
            for (int mt = 0; mt < 4; mt++)
#pragma unroll
                for (int nt = 0; nt < 2; nt++)
                    mma_tf32(o[mt][nt], af[mt], bf[nt]);
        }

        // all warps done reading V buf -> prefetch V(c+1) into B
        __syncthreads();
        if (c + 1 < ntiles) { issueV(c + 1, F_B); CP_COMMIT(); }
    }

    // write O to ctx [B,S,H*DH]
#pragma unroll
    for (int mt = 0; mt < 4; mt++) {
#pragma unroll
        for (int nt = 0; nt < 2; nt++) {
            int s0 = qt * 128 + warpM * 64 + mt * 16 + g;
            int d0 = warpN * 16 + nt * 8 + 2 * t;
#pragma unroll
            for (int half = 0; half < 2; half++) {
                int s = s0 + half * 8;
                size_t base = ((size_t)b * Sn + s) * Dn + h * DHn + d0;
                ctx[base] = o[mt][nt][half * 2 + 0];
                ctx[base + 1] = o[mt][nt][half * 2 + 1];
            }
        }
    }
}

// ---------------------------------------------------------------------------
// Launch
// ---------------------------------------------------------------------------
extern "C" void kernel_launch(void* const* d_in, const int* in_sizes, int n_in,
                              void* d_out, int out_size)
{
    const float* Q  = (const float*)d_in[0];
    const float* K  = (const float*)d_in[1];
    const float* V  = (const float*)d_in[2];
    const float* wq = (const float*)d_in[4];
    const float* bq = (const float*)d_in[5];
    const float* wk = (const float*)d_in[6];
    const float* bk = (const float*)d_in[7];
    const float* wv = (const float*)d_in[8];
    const float* bv = (const float*)d_in[9];
    const float* wo = (const float*)d_in[10];
    const float* bo = (const float*)d_in[11];

    float* out = (float*)d_out;

    float* attn;
    if ((size_t)out_size >= OUT_ELEMS + ATTN_ELEMS) {
        attn = out + OUT_ELEMS;
    } else {
        void* p = nullptr;
        cudaGetSymbolAddress(&p, g_attn_scratch);
        attn = (float*)p;
    }

    float *gq, *gk, *gv, *gctx;
    {
        void* p;
        cudaGetSymbolAddress(&p, g_q);   gq   = (float*)p;
        cudaGetSymbolAddress(&p, g_k);   gk   = (float*)p;
        cudaGetSymbolAddress(&p, g_v);   gv   = (float*)p;
        cudaGetSymbolAddress(&p, g_ctx); gctx = (float*)p;
    }

    cudaFuncSetAttribute(tf32_gemm_kernel,
                         cudaFuncAttributeMaxDynamicSharedMemorySize, GEMM_SMEM);
    cudaFuncSetAttribute(fused_attn_kernel,
                         cudaFuncAttributeMaxDynamicSharedMemorySize, FUSED_SMEM);

    // QKV projections in one launch (grid.z selects which)
    dim3 gqkv(Dn / 128, Mn / 128, 3);   // (8, 64, 3)
    tf32_gemm_kernel<<<gqkv, 256, GEMM_SMEM>>>(
        Q, K, V, wq, wk, wv, bq, bk, bv, gq, gk, gv, 1);

    fused_attn_kernel<<<dim3(NQT, BHn), 256, FUSED_SMEM>>>(gq, gk, gv, attn, gctx);

    // output projection
    dim3 go(Dn / 128, Mn / 128, 1);
    tf32_gemm_kernel<<<go, 256, GEMM_SMEM>>>(
        gctx, gctx, gctx, wo, wo, wo, bo, bo, bo, out, out, out, 0);
}